// round 5
// baseline (speedup 1.0000x reference)
#include <cuda_runtime.h>
#include <cuda_bf16.h>
#include <cstdint>

// Problem constants
#define BB 8
#define CC_ 256
#define OO 256
#define HH 64
#define WW 64
#define HWSZ 4096            // H*W
#define PLANE (HH*WW*CC_)    // 1,048,576 floats per image (NHWC)
#define K9 9

// ---------------- scratch (static __device__ — no allocation) ----------------
__device__ float g_xT[BB * PLANE];            // x in NHWC  [b][y][x][c]   33.5 MB
__device__ float g_wT[K9 * CC_ * OO];         // conv_w as  [k][c][o]       2.36 MB
__device__ unsigned long long g_wO[CC_ * 81]; // offset_w as [c][tap][pair] packed f32x2 (lo=dy-chan, hi=dx-chan)
__device__ float g_py[BB * K9 * HWSZ];        // sampling y coord [b][k][y][x]
__device__ float g_px[BB * K9 * HWSZ];        // sampling x coord

// ---------------- f32x2 helpers (packed dual fp32 FMA, sm_100+) ----------------
__device__ __forceinline__ unsigned long long pack2(float v) {
    unsigned long long r;
    asm("mov.b64 %0, {%1, %1};" : "=l"(r) : "f"(v));
    return r;
}
__device__ __forceinline__ unsigned long long fma2(unsigned long long a,
                                                   unsigned long long b,
                                                   unsigned long long c) {
    unsigned long long d;
    asm("fma.rn.f32x2 %0, %1, %2, %3;" : "=l"(d) : "l"(a), "l"(b), "l"(c));
    return d;
}
__device__ __forceinline__ void unpack2(unsigned long long v, float& lo, float& hi) {
    asm("mov.b64 {%0, %1}, %2;" : "=f"(lo), "=f"(hi) : "l"(v));
}

// ---------------- kernel 1: NCHW -> NHWC transpose of x ----------------
__global__ __launch_bounds__(256) void k_txp(const float* __restrict__ x) {
    __shared__ float t[128][65];
    int b = blockIdx.x >> 6;
    int y = blockIdx.x & 63;
    for (int h = 0; h < 2; ++h) {
        for (int i = threadIdx.x; i < 128 * 64; i += 256) {
            int c  = i >> 6;
            int xx = i & 63;
            t[c][xx] = x[(((b << 8) + (h << 7) + c) << 12) + (y << 6) + xx];
        }
        __syncthreads();
        for (int i = threadIdx.x; i < 64 * 128; i += 256) {
            int xx = i >> 7;
            int c  = i & 127;
            g_xT[((((b << 6) + y) << 6) + xx) * 256 + (h << 7) + c] = t[c][xx];
        }
        __syncthreads();
    }
}

// ---------------- kernel 2: weight re-layouts ----------------
__global__ void k_prep(const float* __restrict__ conv_w, const float* __restrict__ offw) {
    int idx = blockIdx.x * 256 + threadIdx.x;
    if (idx < K9 * CC_ * OO) {
        int k = idx >> 16;
        int c = (idx >> 8) & 255;
        int o = idx & 255;
        g_wT[idx] = conv_w[(o * 256 + c) * 9 + k];
    }
    int j = idx - K9 * CC_ * OO;
    if (j >= 0 && j < CC_ * 81) {
        int c   = j / 81;
        int r   = j - c * 81;
        int tap = r / 9;
        int p   = r - tap * 9;   // p == k : pair (oc=2k -> dy, oc=2k+1 -> dx)
        float lo = offw[((2 * p) * 256 + c) * 9 + tap];
        float hi = offw[((2 * p + 1) * 256 + c) * 9 + tap];
        unsigned long long u = ((unsigned long long)__float_as_uint(hi) << 32) |
                               (unsigned long long)__float_as_uint(lo);
        g_wO[j] = u;
    }
}

// ---------------- kernel 3: offset conv -> sampling coordinates ----------------
// block = (b, row-pair); 128 threads = 128 pixels (2 rows x 64 cols)
__global__ __launch_bounds__(128) void k_offsets(const float* __restrict__ offb) {
    __shared__ float xs[4][66][17];                 // 4 input rows, x=-1..64, 16 c (+pad)
    __shared__ unsigned long long ws[16][81];       // [c][tap*9+pair]

    int blk   = blockIdx.x;
    int b     = blk >> 5;
    int ypair = blk & 31;
    int y0    = ypair << 1;
    int tid   = threadIdx.x;
    int ly    = tid >> 6;
    int lx    = tid & 63;
    int y     = y0 + ly;

    const float* plane = g_xT + ((size_t)b << 20);

    unsigned long long acc[9];
#pragma unroll
    for (int p = 0; p < 9; ++p) acc[p] = 0ull;

    for (int cc = 0; cc < 16; ++cc) {
        int c0 = cc << 4;
        // stage x rows (zero-padded)
        for (int i = tid; i < 1056; i += 128) {
            int r   = i / 264;
            int rem = i - r * 264;
            int j   = rem >> 2;
            int q   = rem & 3;
            int yy  = y0 - 1 + r;
            int xx  = j - 1;
            float4 v = make_float4(0.f, 0.f, 0.f, 0.f);
            if (yy >= 0 && yy < HH && xx >= 0 && xx < WW)
                v = *(const float4*)(plane + ((yy << 6) + xx) * 256 + c0 + (q << 2));
            xs[r][j][(q << 2) + 0] = v.x;
            xs[r][j][(q << 2) + 1] = v.y;
            xs[r][j][(q << 2) + 2] = v.z;
            xs[r][j][(q << 2) + 3] = v.w;
        }
        // stage packed offset weights
        for (int i = tid; i < 1296; i += 128) {
            int c = i / 81;
            int t = i - c * 81;
            ws[c][t] = g_wO[(c0 + c) * 81 + t];
        }
        __syncthreads();

        for (int c = 0; c < 16; ++c) {
#pragma unroll
            for (int tap = 0; tap < 9; ++tap) {
                int dy = tap / 3, dx = tap % 3;
                float v = xs[ly + dy][lx + dx][c];
                unsigned long long v2 = pack2(v);
#pragma unroll
                for (int p = 0; p < 9; ++p)
                    acc[p] = fma2(v2, ws[c][tap * 9 + p], acc[p]);
            }
        }
        __syncthreads();
    }

#pragma unroll
    for (int k = 0; k < 9; ++k) {
        float dyo, dxo;
        unpack2(acc[k], dyo, dxo);
        dyo += offb[2 * k];
        dxo += offb[2 * k + 1];
        int ky = k / 3, kx = k % 3;
        int gi = ((b * 9 + k) << 12) + (y << 6) + lx;
        g_py[gi] = (float)(y - 1 + ky) + dyo;
        g_px[gi] = (float)(lx - 1 + kx) + dxo;
    }
}

// ---------------- kernel 4: fused gather + implicit GEMM ----------------
// block = (b, y): 64 pixels x 256 outputs. 256 threads, 8x8 micro-tile via f32x2.
__global__ __launch_bounds__(256) void k_main(float* __restrict__ out) {
    __shared__ int4   sIdx[576];   // 64 pixels x 9 taps: clamped corner offsets (pre *C)
    __shared__ float4 sW[576];     // bilinear corner weights (zeroed when OOB)
    __shared__ float  A_s[16][64]; // [c-chunk][m]
    __shared__ float  B_s[16][256];// [c-chunk][o]

    int b   = blockIdx.x >> 6;
    int y   = blockIdx.x & 63;
    int tid = threadIdx.x;

    // ---- sampling table ----
    for (int i = tid; i < 576; i += 256) {
        int m = i / 9;
        int k = i - m * 9;
        int gi = ((b * 9 + k) << 12) + (y << 6) + m;
        float py = g_py[gi];
        float px = g_px[gi];
        float fy = floorf(py), fx = floorf(px);
        int y0 = (int)fy, x0 = (int)fx;
        float wy1 = py - fy, wx1 = px - fx;
        float wy0 = 1.f - wy1, wx0 = 1.f - wx1;
        int y1 = y0 + 1, x1 = x0 + 1;
        bool vy0 = (y0 >= 0) && (y0 < HH);
        bool vy1 = (y1 >= 0) && (y1 < HH);
        bool vx0 = (x0 >= 0) && (x0 < WW);
        bool vx1 = (x1 >= 0) && (x1 < WW);
        int cy0 = min(max(y0, 0), HH - 1), cy1 = min(max(y1, 0), HH - 1);
        int cx0 = min(max(x0, 0), WW - 1), cx1 = min(max(x1, 0), WW - 1);
        sIdx[i] = make_int4(((cy0 << 6) + cx0) << 8, ((cy0 << 6) + cx1) << 8,
                            ((cy1 << 6) + cx0) << 8, ((cy1 << 6) + cx1) << 8);
        sW[i] = make_float4((vy0 && vx0) ? wy0 * wx0 : 0.f,
                            (vy0 && vx1) ? wy0 * wx1 : 0.f,
                            (vy1 && vx0) ? wy1 * wx0 : 0.f,
                            (vy1 && vx1) ? wy1 * wx1 : 0.f);
    }
    __syncthreads();

    const float* plane = g_xT + ((size_t)b << 20);

    unsigned long long acc[8][4];
#pragma unroll
    for (int mi = 0; mi < 8; ++mi)
#pragma unroll
        for (int p = 0; p < 4; ++p) acc[mi][p] = 0ull;

    int o0 = (tid & 31) << 3;
    int m0 = (tid >> 5) << 3;
    int mA = tid >> 2;          // staging pixel
    int c4 = (tid & 3) << 2;    // staging c offset within chunk

    for (int cc = 0; cc < 16; ++cc) {        // c-chunk outer -> L1 reuse across k
        int c0 = cc << 4;
        for (int k = 0; k < 9; ++k) {
            // ---- stage A: bilinear-combined channel vectors ----
            {
                int e = mA * 9 + k;
                int4   id = sIdx[e];
                float4 w  = sW[e];
                const float* pb = plane + c0 + c4;
                float4 v00 = *(const float4*)(pb + id.x);
                float4 v01 = *(const float4*)(pb + id.y);
                float4 v10 = *(const float4*)(pb + id.z);
                float4 v11 = *(const float4*)(pb + id.w);
                A_s[c4 + 0][mA] = w.x * v00.x + w.y * v01.x + w.z * v10.x + w.w * v11.x;
                A_s[c4 + 1][mA] = w.x * v00.y + w.y * v01.y + w.z * v10.y + w.w * v11.y;
                A_s[c4 + 2][mA] = w.x * v00.z + w.y * v01.z + w.z * v10.z + w.w * v11.z;
                A_s[c4 + 3][mA] = w.x * v00.w + w.y * v01.w + w.z * v10.w + w.w * v11.w;
            }
            // ---- stage B: conv_w slice [16 c][256 o] ----
            {
                const float4* src = (const float4*)(g_wT + ((k << 8) + c0) * 256);
                float4* dst = (float4*)B_s;
#pragma unroll
                for (int i = 0; i < 4; ++i) dst[tid + i * 256] = src[tid + i * 256];
            }
            __syncthreads();

#pragma unroll
            for (int kk = 0; kk < 16; ++kk) {
                float4 a0 = *(const float4*)&A_s[kk][m0];
                float4 a1 = *(const float4*)&A_s[kk][m0 + 4];
                unsigned long long bb[4];
                *(float4*)&bb[0] = *(const float4*)&B_s[kk][o0];
                *(float4*)&bb[2] = *(const float4*)&B_s[kk][o0 + 4];
                float am[8] = {a0.x, a0.y, a0.z, a0.w, a1.x, a1.y, a1.z, a1.w};
#pragma unroll
                for (int mi = 0; mi < 8; ++mi) {
                    unsigned long long a2 = pack2(am[mi]);
#pragma unroll
                    for (int p = 0; p < 4; ++p)
                        acc[mi][p] = fma2(a2, bb[p], acc[mi][p]);
                }
            }
            __syncthreads();
        }
    }

    // ---- epilogue: NCHW output ----
#pragma unroll
    for (int p = 0; p < 4; ++p) {
#pragma unroll
        for (int h = 0; h < 2; ++h) {
            int o = o0 + 2 * p + h;
            float v[8];
#pragma unroll
            for (int mi = 0; mi < 8; ++mi) {
                float lo, hi;
                unpack2(acc[mi][p], lo, hi);
                v[mi] = h ? hi : lo;
            }
            float* po = out + ((((size_t)b << 8) + o) << 12) + (y << 6) + m0;
            *(float4*)(po)     = make_float4(v[0], v[1], v[2], v[3]);
            *(float4*)(po + 4) = make_float4(v[4], v[5], v[6], v[7]);
        }
    }
}

// ---------------- launch ----------------
extern "C" void kernel_launch(void* const* d_in, const int* in_sizes, int n_in,
                              void* d_out, int out_size) {
    const float* x      = (const float*)d_in[0];  // [8,256,64,64]
    const float* offw   = (const float*)d_in[1];  // [18,256,3,3]
    const float* offb   = (const float*)d_in[2];  // [18]
    const float* conv_w = (const float*)d_in[3];  // [256,256,3,3]
    float* out = (float*)d_out;                   // [8,256,64,64]

    k_txp<<<BB * HH, 256>>>(x);
    k_prep<<<(K9 * CC_ * OO + CC_ * 81 + 255) / 256, 256>>>(conv_w, offw);
    k_offsets<<<BB * (HH / 2), 128>>>(offb);
    k_main<<<BB * HH, 256>>>(out);
}

// round 8
// speedup vs baseline: 1.4902x; 1.4902x over previous
#include <cuda_runtime.h>
#include <cuda_bf16.h>
#include <cstdint>

// Problem constants
#define BB 8
#define CC_ 256
#define OO 256
#define HH 64
#define WW 64
#define HWSZ 4096
#define PLANE (HH*WW*CC_)
#define K9 9

// ---------------- scratch (static __device__ — no allocation) ----------------
__device__ float g_xT[BB * PLANE];            // x in NHWC [b][y][x][c]
__device__ unsigned long long g_wO[CC_ * 81]; // offset_w packed f32x2
__device__ float g_py[BB * K9 * HWSZ];
__device__ float g_px[BB * K9 * HWSZ];
// B operand images, swizzled: [tap*4+ch] -> [o:256][c:64] bf16 (32KB each)
__device__ uint4 g_wBhi[K9 * 4 * 2048];
__device__ uint4 g_wBlo[K9 * 4 * 2048];

// ---------------- helpers ----------------
__device__ __forceinline__ unsigned long long pack2(float v) {
    unsigned long long r; asm("mov.b64 %0, {%1, %1};" : "=l"(r) : "f"(v)); return r;
}
__device__ __forceinline__ unsigned long long fma2(unsigned long long a, unsigned long long b, unsigned long long c) {
    unsigned long long d; asm("fma.rn.f32x2 %0, %1, %2, %3;" : "=l"(d) : "l"(a), "l"(b), "l"(c)); return d;
}
__device__ __forceinline__ void unpack2(unsigned long long v, float& lo, float& hi) {
    asm("mov.b64 {%0, %1}, %2;" : "=f"(lo), "=f"(hi) : "l"(v));
}
__device__ __forceinline__ unsigned smem_u32(const void* p) {
    unsigned a;
    asm("{ .reg .u64 t; cvta.to.shared.u64 t, %1; cvt.u32.u64 %0, t; }" : "=r"(a) : "l"(p));
    return a;
}
__device__ __forceinline__ void ldsm4(unsigned& r0, unsigned& r1, unsigned& r2, unsigned& r3, unsigned addr) {
    asm volatile("ldmatrix.sync.aligned.m8n8.x4.shared.b16 {%0,%1,%2,%3}, [%4];"
                 : "=r"(r0), "=r"(r1), "=r"(r2), "=r"(r3) : "r"(addr));
}
__device__ __forceinline__ void mma16816(float* d, unsigned a0, unsigned a1, unsigned a2, unsigned a3,
                                         unsigned b0, unsigned b1) {
    asm volatile("mma.sync.aligned.m16n8k16.row.col.f32.bf16.bf16.f32 "
                 "{%0,%1,%2,%3}, {%4,%5,%6,%7}, {%8,%9}, {%0,%1,%2,%3};"
                 : "+f"(d[0]), "+f"(d[1]), "+f"(d[2]), "+f"(d[3])
                 : "r"(a0), "r"(a1), "r"(a2), "r"(a3), "r"(b0), "r"(b1));
}
__device__ __forceinline__ void cp16(unsigned dst, const void* src) {
    asm volatile("cp.async.cg.shared.global [%0], [%1], 16;" :: "r"(dst), "l"(src));
}
__device__ __forceinline__ unsigned pack_bf(float a, float b) {
    __nv_bfloat162 t; t.x = __float2bfloat16(a); t.y = __float2bfloat16(b);
    return *(unsigned*)&t;
}

// ---------------- kernel 1: NCHW -> NHWC transpose ----------------
__global__ __launch_bounds__(256) void k_txp(const float* __restrict__ x) {
    __shared__ float t[128][65];
    int b = blockIdx.x >> 6;
    int y = blockIdx.x & 63;
    for (int h = 0; h < 2; ++h) {
        for (int i = threadIdx.x; i < 128 * 64; i += 256) {
            int c = i >> 6, xx = i & 63;
            t[c][xx] = x[(((b << 8) + (h << 7) + c) << 12) + (y << 6) + xx];
        }
        __syncthreads();
        for (int i = threadIdx.x; i < 64 * 128; i += 256) {
            int xx = i >> 7, c = i & 127;
            g_xT[((((b << 6) + y) << 6) + xx) * 256 + (h << 7) + c] = t[c][xx];
        }
        __syncthreads();
    }
}

// ---------------- kernel 2: weight prep ----------------
__global__ void k_prep(const float* __restrict__ conv_w, const float* __restrict__ offw) {
    int idx = blockIdx.x * 256 + threadIdx.x;
    if (idx < K9 * 4 * 256 * 64) {
        int c   = idx & 63;
        int o   = (idx >> 6) & 255;
        int ch  = (idx >> 14) & 3;
        int tap = idx >> 16;
        float f = conv_w[(o * 256 + (ch << 6) + c) * 9 + tap];
        __nv_bfloat16 hi = __float2bfloat16(f);
        __nv_bfloat16 lo = __float2bfloat16(f - __bfloat162float(hi));
        int img = tap * 4 + ch;
        unsigned off = (unsigned)((o << 7) + (c << 1));
        off ^= (unsigned)((o & 7) << 4);               // ldmatrix-friendly XOR swizzle
        ((__nv_bfloat16*)g_wBhi)[img * 16384 + (off >> 1)] = hi;
        ((__nv_bfloat16*)g_wBlo)[img * 16384 + (off >> 1)] = lo;
    }
    int j = idx - K9 * 4 * 256 * 64;
    if (j >= 0 && j < CC_ * 81) {
        int c = j / 81;
        int r = j - c * 81;
        int tap = r / 9;
        int p = r - tap * 9;
        float lo = offw[((2 * p) * 256 + c) * 9 + tap];
        float hi = offw[((2 * p + 1) * 256 + c) * 9 + tap];
        g_wO[j] = ((unsigned long long)__float_as_uint(hi) << 32) | (unsigned long long)__float_as_uint(lo);
    }
}

// ---------------- kernel 3: offset conv -> sampling coords ----------------
__global__ __launch_bounds__(128) void k_offsets(const float* __restrict__ offb) {
    __shared__ float xs[4][66][17];
    __shared__ unsigned long long ws[16][81];

    int blk = blockIdx.x;
    int b = blk >> 5;
    int y0 = (blk & 31) << 1;
    int tid = threadIdx.x;
    int ly = tid >> 6, lx = tid & 63;
    int y = y0 + ly;
    const float* plane = g_xT + ((size_t)b << 20);

    unsigned long long acc[9];
#pragma unroll
    for (int p = 0; p < 9; ++p) acc[p] = 0ull;

    for (int cc = 0; cc < 16; ++cc) {
        int c0 = cc << 4;
        for (int i = tid; i < 1056; i += 128) {
            int r = i / 264, rem = i - r * 264;
            int jj = rem >> 2, q = rem & 3;
            int yy = y0 - 1 + r, xx = jj - 1;
            float4 v = make_float4(0.f, 0.f, 0.f, 0.f);
            if (yy >= 0 && yy < HH && xx >= 0 && xx < WW)
                v = *(const float4*)(plane + ((yy << 6) + xx) * 256 + c0 + (q << 2));
            xs[r][jj][(q << 2) + 0] = v.x; xs[r][jj][(q << 2) + 1] = v.y;
            xs[r][jj][(q << 2) + 2] = v.z; xs[r][jj][(q << 2) + 3] = v.w;
        }
        for (int i = tid; i < 1296; i += 128) {
            int c = i / 81, t = i - c * 81;
            ws[c][t] = g_wO[(c0 + c) * 81 + t];
        }
        __syncthreads();
        for (int c = 0; c < 16; ++c) {
#pragma unroll
            for (int tap = 0; tap < 9; ++tap) {
                unsigned long long v2 = pack2(xs[ly + tap / 3][lx + tap % 3][c]);
#pragma unroll
                for (int p = 0; p < 9; ++p) acc[p] = fma2(v2, ws[c][tap * 9 + p], acc[p]);
            }
        }
        __syncthreads();
    }
#pragma unroll
    for (int k = 0; k < 9; ++k) {
        float dyo, dxo; unpack2(acc[k], dyo, dxo);
        dyo += offb[2 * k]; dxo += offb[2 * k + 1];
        int gi = ((b * 9 + k) << 12) + (y << 6) + lx;
        g_py[gi] = (float)(y - 1 + k / 3) + dyo;
        g_px[gi] = (float)(lx - 1 + k % 3) + dxo;
    }
}

// ---------------- kernel 4: fused gather + HMMA implicit GEMM ----------------
// block = (b, row-pair): M=128 pixels, N=256 outputs; 8 warps in 2(M)x4(N), 64x64 tiles
#define SM_SIDX  0                        // int4[1152]   18432 B
#define SM_SW    18432                    // float4[1152] 18432 B
#define SM_AHI   36864                    // 16 KB
#define SM_ALO   53248                    // 16 KB
#define SM_BHI   69632                    // 32 KB
#define SM_BLO   102400                   // 32 KB
#define SM_TOTAL 135168

__global__ __launch_bounds__(256, 1) void k_main(float* __restrict__ out) {
    extern __shared__ char smem[];
    unsigned sb = smem_u32(smem);
    int tid = threadIdx.x;
    int w = tid >> 5, lid = tid & 31;
    int b = blockIdx.x >> 5;
    int y0 = (blockIdx.x & 31) << 1;

    // ---- sampling tables: 128 px x 9 taps ----
    int4*   sIdx = (int4*)(smem + SM_SIDX);
    float4* sW   = (float4*)(smem + SM_SW);
    for (int i = tid; i < 1152; i += 256) {
        int m = i / 9, k = i - m * 9;
        int gi = ((b * 9 + k) << 12) + ((y0 + (m >> 6)) << 6) + (m & 63);
        float py = g_py[gi], px = g_px[gi];
        float fy = floorf(py), fx = floorf(px);
        int iy0 = (int)fy, ix0 = (int)fx;
        float wy1 = py - fy, wx1 = px - fx;
        float wy0 = 1.f - wy1, wx0 = 1.f - wx1;
        int iy1 = iy0 + 1, ix1 = ix0 + 1;
        bool vy0 = (iy0 >= 0) && (iy0 < HH), vy1 = (iy1 >= 0) && (iy1 < HH);
        bool vx0 = (ix0 >= 0) && (ix0 < WW), vx1 = (ix1 >= 0) && (ix1 < WW);
        int cy0 = min(max(iy0, 0), HH - 1), cy1 = min(max(iy1, 0), HH - 1);
        int cx0 = min(max(ix0, 0), WW - 1), cx1 = min(max(ix1, 0), WW - 1);
        sIdx[i] = make_int4(((cy0 << 6) + cx0) << 8, ((cy0 << 6) + cx1) << 8,
                            ((cy1 << 6) + cx0) << 8, ((cy1 << 6) + cx1) << 8);
        sW[i] = make_float4((vy0 && vx0) ? wy0 * wx0 : 0.f, (vy0 && vx1) ? wy0 * wx1 : 0.f,
                            (vy1 && vx0) ? wy1 * wx0 : 0.f, (vy1 && vx1) ? wy1 * wx1 : 0.f);
    }
    __syncthreads();

    const float* plane = g_xT + ((size_t)b << 20);
    int mA = tid >> 1;                  // staging pixel 0..127
    int chalf = (tid & 1) << 5;         // 0 or 32

    // per-lane ldmatrix address pieces
    int warpM = w >> 2, warpN = w & 3;
    unsigned xorS   = (unsigned)((lid & 7) << 4);
    unsigned aBase  = (unsigned)(((warpM << 6) + (lid & 15)) << 7) + (unsigned)((lid >> 4) << 4);
    unsigned bBase  = (unsigned)(((warpN << 6) + (lid & 7) + ((lid & 16) ? 8 : 0)) << 7)
                    + (unsigned)(((lid >> 3) & 1) << 4);

    float acc[4][8][4];
#pragma unroll
    for (int mi = 0; mi < 4; ++mi)
#pragma unroll
        for (int nf = 0; nf < 8; ++nf)
#pragma unroll
            for (int q = 0; q < 4; ++q) acc[mi][nf][q] = 0.f;

    for (int ch = 0; ch < 4; ++ch) {
        int c0 = ch << 6;
        for (int tap = 0; tap < 9; ++tap) {
            // ---- issue B copy (cp.async, pre-swizzled) ----
            {
                const uint4* sh = g_wBhi + (tap * 4 + ch) * 2048;
                const uint4* sl = g_wBlo + (tap * 4 + ch) * 2048;
#pragma unroll
                for (int i = 0; i < 8; ++i) {
                    cp16(sb + SM_BHI + ((tid + i * 256) << 4), sh + tid + i * 256);
                    cp16(sb + SM_BLO + ((tid + i * 256) << 4), sl + tid + i * 256);
                }
                asm volatile("cp.async.commit_group;" ::: "memory");
            }
            // ---- stage A (bilinear gather -> bf16 hi/lo, swizzled) ----
            {
                int e = mA * 9 + tap;
                int4 id = sIdx[e];
                float4 wv = sW[e];
                const float* pb = plane + c0 + chalf;
                unsigned rowb = (unsigned)(mA << 7) + (unsigned)(chalf << 1);
                unsigned xm = (unsigned)((mA & 7) << 4);
#pragma unroll
                for (int j = 0; j < 8; ++j) {
                    const float* p4 = pb + (j << 2);
                    float4 v00 = *(const float4*)(p4 + id.x);
                    float4 v01 = *(const float4*)(p4 + id.y);
                    float4 v10 = *(const float4*)(p4 + id.z);
                    float4 v11 = *(const float4*)(p4 + id.w);
                    float s0 = wv.x * v00.x + wv.y * v01.x + wv.z * v10.x + wv.w * v11.x;
                    float s1 = wv.x * v00.y + wv.y * v01.y + wv.z * v10.y + wv.w * v11.y;
                    float s2 = wv.x * v00.z + wv.y * v01.z + wv.z * v10.z + wv.w * v11.z;
                    float s3 = wv.x * v00.w + wv.y * v01.w + wv.z * v10.w + wv.w * v11.w;
                    __nv_bfloat16 h0 = __float2bfloat16(s0), h1 = __float2bfloat16(s1);
                    __nv_bfloat16 h2 = __float2bfloat16(s2), h3 = __float2bfloat16(s3);
                    float l0 = s0 - __bfloat162float(h0), l1 = s1 - __bfloat162float(h1);
                    float l2 = s2 - __bfloat162float(h2), l3 = s3 - __bfloat162float(h3);
                    unsigned off = (rowb + (unsigned)(j << 3)) ^ xm;
                    uint2 uh, ul;
                    { __nv_bfloat162 t0; t0.x = h0; t0.y = h1; uh.x = *(unsigned*)&t0;
                      __nv_bfloat162 t1; t1.x = h2; t1.y = h3; uh.y = *(unsigned*)&t1; }
                    ul.x = pack_bf(l0, l1); ul.y = pack_bf(l2, l3);
                    *(uint2*)(smem + SM_AHI + off) = uh;
                    *(uint2*)(smem + SM_ALO + off) = ul;
                }
            }
            asm volatile("cp.async.wait_group 0;" ::: "memory");
            __syncthreads();

            // ---- HMMA mainloop: K=64 -> 4 k16 steps, 3 passes (hh, hl, lh) ----
#pragma unroll
            for (int ks = 0; ks < 4; ++ks) {
                unsigned aoff = aBase + (unsigned)(ks << 5);
                unsigned ah[4][4], al[4][4];
#pragma unroll
                for (int mi = 0; mi < 4; ++mi) {
                    unsigned lin = (aoff + (unsigned)(mi << 11)) ^ xorS;
                    ldsm4(ah[mi][0], ah[mi][1], ah[mi][2], ah[mi][3], sb + SM_AHI + lin);
                    ldsm4(al[mi][0], al[mi][1], al[mi][2], al[mi][3], sb + SM_ALO + lin);
                }
#pragma unroll
                for (int nh = 0; nh < 2; ++nh) {
                    unsigned bh[4][2], bl[4][2];
#pragma unroll
                    for (int n16 = 0; n16 < 2; ++n16) {
                        unsigned lin = (bBase + (unsigned)(ks << 5) + (unsigned)(nh << 12)
                                        + (unsigned)(n16 << 11)) ^ xorS;
                        unsigned r0, r1, r2, r3;
                        ldsm4(r0, r1, r2, r3, sb + SM_BHI + lin);
                        bh[n16 * 2 + 0][0] = r0; bh[n16 * 2 + 0][1] = r1;
                        bh[n16 * 2 + 1][0] = r2; bh[n16 * 2 + 1][1] = r3;
                        ldsm4(r0, r1, r2, r3, sb + SM_BLO + lin);
                        bl[n16 * 2 + 0][0] = r0; bl[n16 * 2 + 0][1] = r1;
                        bl[n16 * 2 + 1][0] = r2; bl[n16 * 2 + 1][1] = r3;
                    }
#pragma unroll
                    for (int mi = 0; mi < 4; ++mi)
#pragma unroll
                        for (int nf = 0; nf < 4; ++nf) {
                            float* d = acc[mi][nh * 4 + nf];
                            mma16816(d, ah[mi][0], ah[mi][1], ah[mi][2], ah[mi][3],
                                     bh[nf][0], bh[nf][1]);
                            mma16816(d, ah[mi][0], ah[mi][1], ah[mi][2], ah[mi][3],
                                     bl[nf][0], bl[nf][1]);
                            mma16816(d, al[mi][0], al[mi][1], al[mi][2], al[mi][3],
                                     bh[nf][0], bh[nf][1]);
                        }
                }
            }
            __syncthreads();
        }
    }

    // ---- epilogue: NCHW scatter from D fragments ----
    {
        int g = lid >> 2, t = lid & 3;
        int y = y0 + warpM;
        float* pb = out + ((size_t)b << 20) + (y << 6);
#pragma unroll
        for (int mi = 0; mi < 4; ++mi) {
            int x0p = (mi << 4) + g;
#pragma unroll
            for (int nf = 0; nf < 8; ++nf) {
                int o = (warpN << 6) + (nf << 3) + (t << 1);
                float* p0 = pb + ((size_t)o << 12);
                p0[x0p]            = acc[mi][nf][0];
                p0[4096 + x0p]     = acc[mi][nf][1];
                p0[x0p + 8]        = acc[mi][nf][2];
                p0[4096 + x0p + 8] = acc[mi][nf][3];
            }
        }
    }
}

// ---------------- launch ----------------
extern "C" void kernel_launch(void* const* d_in, const int* in_sizes, int n_in,
                              void* d_out, int out_size) {
    const float* x      = (const float*)d_in[0];
    const float* offw   = (const float*)d_in[1];
    const float* offb   = (const float*)d_in[2];
    const float* conv_w = (const float*)d_in[3];
    float* out = (float*)d_out;

    static int smem_set = 0;
    if (!smem_set) {
        cudaFuncSetAttribute(k_main, cudaFuncAttributeMaxDynamicSharedMemorySize, SM_TOTAL);
        smem_set = 1;
    }

    k_txp<<<BB * HH, 256>>>(x);
    k_prep<<<(K9 * 4 * 256 * 64 + CC_ * 81 + 255) / 256, 256>>>(conv_w, offw);
    k_offsets<<<BB * (HH / 2), 128>>>(offb);
    k_main<<<BB * 32, 256, SM_TOTAL>>>(out);
}

// round 9
// speedup vs baseline: 1.5813x; 1.0612x over previous
#include <cuda_runtime.h>
#include <cuda_bf16.h>
#include <cstdint>

// Problem constants
#define BB 8
#define CC_ 256
#define OO 256
#define HH 64
#define WW 64
#define HWSZ 4096
#define PLANE (HH*WW*CC_)
#define K9 9

// ---------------- scratch (static __device__ — no allocation) ----------------
__device__ float g_xT[BB * PLANE];            // x in NHWC [b][y][x][c]
__device__ unsigned long long g_wO[CC_ * 81]; // offset_w packed f32x2
__device__ float g_py[BB * K9 * HWSZ];
__device__ float g_px[BB * K9 * HWSZ];
// B operand images, swizzled: [tap*4+ch] -> [o:256][c:64] bf16 (32KB each)
__device__ uint4 g_wBhi[K9 * 4 * 2048];
__device__ uint4 g_wBlo[K9 * 4 * 2048];

// ---------------- helpers ----------------
__device__ __forceinline__ unsigned long long pack2(float v) {
    unsigned long long r; asm("mov.b64 %0, {%1, %1};" : "=l"(r) : "f"(v)); return r;
}
__device__ __forceinline__ unsigned long long fma2(unsigned long long a, unsigned long long b, unsigned long long c) {
    unsigned long long d; asm("fma.rn.f32x2 %0, %1, %2, %3;" : "=l"(d) : "l"(a), "l"(b), "l"(c)); return d;
}
__device__ __forceinline__ void unpack2(unsigned long long v, float& lo, float& hi) {
    asm("mov.b64 {%0, %1}, %2;" : "=f"(lo), "=f"(hi) : "l"(v));
}
__device__ __forceinline__ unsigned smem_u32(const void* p) {
    unsigned a;
    asm("{ .reg .u64 t; cvta.to.shared.u64 t, %1; cvt.u32.u64 %0, t; }" : "=r"(a) : "l"(p));
    return a;
}
__device__ __forceinline__ void ldsm4(unsigned& r0, unsigned& r1, unsigned& r2, unsigned& r3, unsigned addr) {
    asm volatile("ldmatrix.sync.aligned.m8n8.x4.shared.b16 {%0,%1,%2,%3}, [%4];"
                 : "=r"(r0), "=r"(r1), "=r"(r2), "=r"(r3) : "r"(addr));
}
__device__ __forceinline__ void mma16816(float* d, unsigned a0, unsigned a1, unsigned a2, unsigned a3,
                                         unsigned b0, unsigned b1) {
    asm volatile("mma.sync.aligned.m16n8k16.row.col.f32.bf16.bf16.f32 "
                 "{%0,%1,%2,%3}, {%4,%5,%6,%7}, {%8,%9}, {%0,%1,%2,%3};"
                 : "+f"(d[0]), "+f"(d[1]), "+f"(d[2]), "+f"(d[3])
                 : "r"(a0), "r"(a1), "r"(a2), "r"(a3), "r"(b0), "r"(b1));
}
__device__ __forceinline__ void cp16(unsigned dst, const void* src) {
    asm volatile("cp.async.cg.shared.global [%0], [%1], 16;" :: "r"(dst), "l"(src));
}
__device__ __forceinline__ unsigned pack_bf(float a, float b) {
    __nv_bfloat162 t; t.x = __float2bfloat16(a); t.y = __float2bfloat16(b);
    return *(unsigned*)&t;
}
__device__ __forceinline__ void samp(float py, float px, int4& id, float4& wv) {
    float fy = floorf(py), fx = floorf(px);
    int iy0 = (int)fy, ix0 = (int)fx;
    float wy1 = py - fy, wx1 = px - fx;
    float wy0 = 1.f - wy1, wx0 = 1.f - wx1;
    int iy1 = iy0 + 1, ix1 = ix0 + 1;
    bool vy0 = (iy0 >= 0) && (iy0 < HH), vy1 = (iy1 >= 0) && (iy1 < HH);
    bool vx0 = (ix0 >= 0) && (ix0 < WW), vx1 = (ix1 >= 0) && (ix1 < WW);
    int cy0 = min(max(iy0, 0), HH - 1), cy1 = min(max(iy1, 0), HH - 1);
    int cx0 = min(max(ix0, 0), WW - 1), cx1 = min(max(ix1, 0), WW - 1);
    id = make_int4(((cy0 << 6) + cx0) << 8, ((cy0 << 6) + cx1) << 8,
                   ((cy1 << 6) + cx0) << 8, ((cy1 << 6) + cx1) << 8);
    wv = make_float4((vy0 && vx0) ? wy0 * wx0 : 0.f, (vy0 && vx1) ? wy0 * wx1 : 0.f,
                     (vy1 && vx0) ? wy1 * wx0 : 0.f, (vy1 && vx1) ? wy1 * wx1 : 0.f);
}

// ---------------- kernel 1: NCHW -> NHWC transpose ----------------
__global__ __launch_bounds__(256) void k_txp(const float* __restrict__ x) {
    __shared__ float t[128][65];
    int b = blockIdx.x >> 6;
    int y = blockIdx.x & 63;
    for (int h = 0; h < 2; ++h) {
        for (int i = threadIdx.x; i < 128 * 64; i += 256) {
            int c = i >> 6, xx = i & 63;
            t[c][xx] = x[(((b << 8) + (h << 7) + c) << 12) + (y << 6) + xx];
        }
        __syncthreads();
        for (int i = threadIdx.x; i < 64 * 128; i += 256) {
            int xx = i >> 7, c = i & 127;
            g_xT[((((b << 6) + y) << 6) + xx) * 256 + (h << 7) + c] = t[c][xx];
        }
        __syncthreads();
    }
}

// ---------------- kernel 2: weight prep ----------------
__global__ void k_prep(const float* __restrict__ conv_w, const float* __restrict__ offw) {
    int idx = blockIdx.x * 256 + threadIdx.x;
    if (idx < K9 * 4 * 256 * 64) {
        int c   = idx & 63;
        int o   = (idx >> 6) & 255;
        int ch  = (idx >> 14) & 3;
        int tap = idx >> 16;
        float f = conv_w[(o * 256 + (ch << 6) + c) * 9 + tap];
        __nv_bfloat16 hi = __float2bfloat16(f);
        __nv_bfloat16 lo = __float2bfloat16(f - __bfloat162float(hi));
        int img = tap * 4 + ch;
        unsigned off = (unsigned)((o << 7) + (c << 1));
        off ^= (unsigned)((o & 7) << 4);               // ldmatrix-friendly XOR swizzle
        ((__nv_bfloat16*)g_wBhi)[img * 16384 + (off >> 1)] = hi;
        ((__nv_bfloat16*)g_wBlo)[img * 16384 + (off >> 1)] = lo;
    }
    int j = idx - K9 * 4 * 256 * 64;
    if (j >= 0 && j < CC_ * 81) {
        int c = j / 81;
        int r = j - c * 81;
        int tap = r / 9;
        int p = r - tap * 9;
        float lo = offw[((2 * p) * 256 + c) * 9 + tap];
        float hi = offw[((2 * p + 1) * 256 + c) * 9 + tap];
        g_wO[j] = ((unsigned long long)__float_as_uint(hi) << 32) | (unsigned long long)__float_as_uint(lo);
    }
}

// ---------------- kernel 3: offset conv -> sampling coords (4 rows/block) ----------------
__global__ __launch_bounds__(256) void k_offsets(const float* __restrict__ offb) {
    __shared__ float xs[6][66][17];
    __shared__ unsigned long long ws[16][81];

    int blk = blockIdx.x;
    int b = blk >> 4;
    int y0 = (blk & 15) << 2;
    int tid = threadIdx.x;
    int ly = tid >> 6, lx = tid & 63;
    int y = y0 + ly;
    const float* plane = g_xT + ((size_t)b << 20);

    unsigned long long acc[9];
#pragma unroll
    for (int p = 0; p < 9; ++p) acc[p] = 0ull;

    for (int cc = 0; cc < 16; ++cc) {
        int c0 = cc << 4;
        for (int i = tid; i < 1584; i += 256) {
            int r = i / 264, rem = i - r * 264;
            int jj = rem >> 2, q = rem & 3;
            int yy = y0 - 1 + r, xx = jj - 1;
            float4 v = make_float4(0.f, 0.f, 0.f, 0.f);
            if (yy >= 0 && yy < HH && xx >= 0 && xx < WW)
                v = *(const float4*)(plane + ((yy << 6) + xx) * 256 + c0 + (q << 2));
            xs[r][jj][(q << 2) + 0] = v.x; xs[r][jj][(q << 2) + 1] = v.y;
            xs[r][jj][(q << 2) + 2] = v.z; xs[r][jj][(q << 2) + 3] = v.w;
        }
        for (int i = tid; i < 1296; i += 256) {
            int c = i / 81, t = i - c * 81;
            ws[c][t] = g_wO[(c0 + c) * 81 + t];
        }
        __syncthreads();
        for (int c = 0; c < 16; ++c) {
#pragma unroll
            for (int tap = 0; tap < 9; ++tap) {
                unsigned long long v2 = pack2(xs[ly + tap / 3][lx + tap % 3][c]);
#pragma unroll
                for (int p = 0; p < 9; ++p) acc[p] = fma2(v2, ws[c][tap * 9 + p], acc[p]);
            }
        }
        __syncthreads();
    }
#pragma unroll
    for (int k = 0; k < 9; ++k) {
        float dyo, dxo; unpack2(acc[k], dyo, dxo);
        dyo += offb[2 * k]; dxo += offb[2 * k + 1];
        int gi = ((b * 9 + k) << 12) + (y << 6) + lx;
        g_py[gi] = (float)(y - 1 + k / 3) + dyo;
        g_px[gi] = (float)(lx - 1 + k % 3) + dxo;
    }
}

// ---------------- kernel 4: pipelined fused gather + HMMA implicit GEMM ----------------
// block = (b, row-pair): M=128, N=256; 8 warps 2Mx4N, 64x64 warp tiles.
// smem: A double (hi+lo 32KB/stage), Bhi double (32KB/stage), Blo single (32KB) = 160KB
#define SM_A     0
#define SM_BHI   65536
#define SM_BLO   131072
#define SM_TOTAL 163840

__global__ __launch_bounds__(256, 1) void k_main(float* __restrict__ out) {
    extern __shared__ char smem[];
    unsigned sb = smem_u32(smem);
    int tid = threadIdx.x;
    int w = tid >> 5, lid = tid & 31;
    int b = blockIdx.x >> 5;
    int y0 = (blockIdx.x & 31) << 1;

    const float* plane = g_xT + ((size_t)b << 20);
    int mA = tid >> 1;
    int chalf = (tid & 1) << 5;
    unsigned rowb = (unsigned)(mA << 7) + (unsigned)(chalf << 1);
    unsigned xm = (unsigned)((mA & 7) << 4);
    int gi0 = ((b * 9) << 12) + ((y0 + (mA >> 6)) << 6) + (mA & 63);

    int warpM = w >> 2, warpN = w & 3;
    unsigned xorS  = (unsigned)((lid & 7) << 4);
    unsigned aBase = (unsigned)(((warpM << 6) + (lid & 15)) << 7) + (unsigned)((lid >> 4) << 4);
    unsigned bBase = (unsigned)(((warpN << 6) + (lid & 7) + ((lid & 16) ? 8 : 0)) << 7)
                   + (unsigned)(((lid >> 3) & 1) << 4);

    float acc[4][8][4];
#pragma unroll
    for (int mi = 0; mi < 4; ++mi)
#pragma unroll
        for (int nf = 0; nf < 8; ++nf)
#pragma unroll
            for (int q = 0; q < 4; ++q) acc[mi][nf][q] = 0.f;

    // ---- prologue: stage iter 0 (ch0, tap0) ----
    {
#pragma unroll
        for (int i = 0; i < 8; ++i) {
            cp16(sb + SM_BHI + ((tid + i * 256) << 4), g_wBhi + tid + i * 256);
            cp16(sb + SM_BLO + ((tid + i * 256) << 4), g_wBlo + tid + i * 256);
        }
        asm volatile("cp.async.commit_group;" ::: "memory");
        int4 id; float4 wv;
        samp(g_py[gi0], g_px[gi0], id, wv);
        const float* pb = plane + chalf;
#pragma unroll
        for (int j = 0; j < 8; ++j) {
            const float* p4 = pb + (j << 2);
            float4 v00 = *(const float4*)(p4 + id.x);
            float4 v01 = *(const float4*)(p4 + id.y);
            float4 v10 = *(const float4*)(p4 + id.z);
            float4 v11 = *(const float4*)(p4 + id.w);
            float s0 = wv.x * v00.x + wv.y * v01.x + wv.z * v10.x + wv.w * v11.x;
            float s1 = wv.x * v00.y + wv.y * v01.y + wv.z * v10.y + wv.w * v11.y;
            float s2 = wv.x * v00.z + wv.y * v01.z + wv.z * v10.z + wv.w * v11.z;
            float s3 = wv.x * v00.w + wv.y * v01.w + wv.z * v10.w + wv.w * v11.w;
            __nv_bfloat16 h0 = __float2bfloat16(s0), h1 = __float2bfloat16(s1);
            __nv_bfloat16 h2 = __float2bfloat16(s2), h3 = __float2bfloat16(s3);
            unsigned off = (rowb + (unsigned)(j << 3)) ^ xm;
            uint2 uh, ul;
            { __nv_bfloat162 t0; t0.x = h0; t0.y = h1; uh.x = *(unsigned*)&t0;
              __nv_bfloat162 t1; t1.x = h2; t1.y = h3; uh.y = *(unsigned*)&t1; }
            ul.x = pack_bf(s0 - __bfloat162float(h0), s1 - __bfloat162float(h1));
            ul.y = pack_bf(s2 - __bfloat162float(h2), s3 - __bfloat162float(h3));
            *(uint2*)(smem + SM_A + off)         = uh;
            *(uint2*)(smem + SM_A + 16384 + off) = ul;
        }
        asm volatile("cp.async.wait_group 0;" ::: "memory");
        __syncthreads();
    }

    int tap = 0, ch = 0;
    for (int it = 0; it < 36; ++it) {
        int tapn = tap + 1, chn = ch;
        if (tapn == 9) { tapn = 0; chn = ch + 1; }
        bool hn = (chn < 4);
        int cur = it & 1, nxt = cur ^ 1;
        unsigned aCur = SM_A + (unsigned)(cur << 15);
        unsigned aNxt = SM_A + (unsigned)(nxt << 15);
        unsigned bhC  = SM_BHI + (unsigned)(cur << 15);
        unsigned bhN  = SM_BHI + (unsigned)(nxt << 15);
        int imgN = tapn * 4 + chn;

        // issue Bhi(next) copy — overlaps whole iteration
        if (hn) {
            const uint4* src = g_wBhi + imgN * 2048;
#pragma unroll
            for (int i = 0; i < 8; ++i)
                cp16(sb + bhN + ((tid + i * 256) << 4), src + tid + i * 256);
            asm volatile("cp.async.commit_group;" ::: "memory");
        }

        // ---- Phase 1: hl pass (Ahi x Blo) — only consumer of SM_BLO ----
#pragma unroll
        for (int ks = 0; ks < 4; ++ks) {
            unsigned ah[4][4];
#pragma unroll
            for (int mi = 0; mi < 4; ++mi) {
                unsigned lin = (aBase + (unsigned)(ks << 5) + (unsigned)(mi << 11)) ^ xorS;
                ldsm4(ah[mi][0], ah[mi][1], ah[mi][2], ah[mi][3], sb + aCur + lin);
            }
#pragma unroll
            for (int nh = 0; nh < 2; ++nh) {
                unsigned bl[4][2];
#pragma unroll
                for (int n16 = 0; n16 < 2; ++n16) {
                    unsigned lin = (bBase + (unsigned)(ks << 5) + (unsigned)(nh << 12)
                                    + (unsigned)(n16 << 11)) ^ xorS;
                    unsigned r0, r1, r2, r3;
                    ldsm4(r0, r1, r2, r3, sb + SM_BLO + lin);
                    bl[n16 * 2 + 0][0] = r0; bl[n16 * 2 + 0][1] = r1;
                    bl[n16 * 2 + 1][0] = r2; bl[n16 * 2 + 1][1] = r3;
                }
#pragma unroll
                for (int mi = 0; mi < 4; ++mi)
#pragma unroll
                    for (int nf = 0; nf < 4; ++nf)
                        mma16816(acc[mi][nh * 4 + nf], ah[mi][0], ah[mi][1], ah[mi][2], ah[mi][3],
                                 bl[nf][0], bl[nf][1]);
            }
        }
        __syncthreads();   // all warps done reading SM_BLO

        // issue Blo(next) copy — overlaps Phase 2
        if (hn) {
            const uint4* src = g_wBlo + imgN * 2048;
#pragma unroll
            for (int i = 0; i < 8; ++i)
                cp16(sb + SM_BLO + ((tid + i * 256) << 4), src + tid + i * 256);
            asm volatile("cp.async.commit_group;" ::: "memory");
        }

        // staging prep for next iter
        int4 id; float4 wv;
        const float* pb = plane;
        if (hn) {
            samp(g_py[gi0 + (tapn << 12)], g_px[gi0 + (tapn << 12)], id, wv);
            pb = plane + (chn << 6) + chalf;
        }

        // ---- Phase 2: hh + lh passes, interleaved with A staging ----
#pragma unroll
        for (int seg = 0; seg < 4; ++seg) {
            float4 r[8];
            if (hn) {
                const float* p40 = pb + (unsigned)((seg * 2) << 2);
                const float* p41 = p40 + 4;
                r[0] = *(const float4*)(p40 + id.x); r[1] = *(const float4*)(p40 + id.y);
                r[2] = *(const float4*)(p40 + id.z); r[3] = *(const float4*)(p40 + id.w);
                r[4] = *(const float4*)(p41 + id.x); r[5] = *(const float4*)(p41 + id.y);
                r[6] = *(const float4*)(p41 + id.z); r[7] = *(const float4*)(p41 + id.w);
            }
            {
                int ks = seg;
                unsigned ah[4][4], al[4][4];
#pragma unroll
                for (int mi = 0; mi < 4; ++mi) {
                    unsigned lin = (aBase + (unsigned)(ks << 5) + (unsigned)(mi << 11)) ^ xorS;
                    ldsm4(ah[mi][0], ah[mi][1], ah[mi][2], ah[mi][3], sb + aCur + lin);
                    ldsm4(al[mi][0], al[mi][1], al[mi][2], al[mi][3], sb + aCur + 16384 + lin);
                }
#pragma unroll
                for (int nh = 0; nh < 2; ++nh) {
                    unsigned bh[4][2];
#pragma unroll
                    for (int n16 = 0; n16 < 2; ++n16) {
                        unsigned lin = (bBase + (unsigned)(ks << 5) + (unsigned)(nh << 12)
                                        + (unsigned)(n16 << 11)) ^ xorS;
                        unsigned r0, r1, r2, r3;
                        ldsm4(r0, r1, r2, r3, sb + bhC + lin);
                        bh[n16 * 2 + 0][0] = r0; bh[n16 * 2 + 0][1] = r1;
                        bh[n16 * 2 + 1][0] = r2; bh[n16 * 2 + 1][1] = r3;
                    }
#pragma unroll
                    for (int mi = 0; mi < 4; ++mi)
#pragma unroll
                        for (int nf = 0; nf < 4; ++nf) {
                            float* d = acc[mi][nh * 4 + nf];
                            mma16816(d, ah[mi][0], ah[mi][1], ah[mi][2], ah[mi][3],
                                     bh[nf][0], bh[nf][1]);
                            mma16816(d, al[mi][0], al[mi][1], al[mi][2], al[mi][3],
                                     bh[nf][0], bh[nf][1]);
                        }
                }
            }
            if (hn) {
#pragma unroll
                for (int h = 0; h < 2; ++h) {
                    float4 v00 = r[h * 4 + 0], v01 = r[h * 4 + 1];
                    float4 v10 = r[h * 4 + 2], v11 = r[h * 4 + 3];
                    float s0 = wv.x * v00.x + wv.y * v01.x + wv.z * v10.x + wv.w * v11.x;
                    float s1 = wv.x * v00.y + wv.y * v01.y + wv.z * v10.y + wv.w * v11.y;
                    float s2 = wv.x * v00.z + wv.y * v01.z + wv.z * v10.z + wv.w * v11.z;
                    float s3 = wv.x * v00.w + wv.y * v01.w + wv.z * v10.w + wv.w * v11.w;
                    __nv_bfloat16 h0 = __float2bfloat16(s0), h1 = __float2bfloat16(s1);
                    __nv_bfloat16 h2 = __float2bfloat16(s2), h3 = __float2bfloat16(s3);
                    unsigned off = (rowb + (unsigned)((seg * 2 + h) << 3)) ^ xm;
                    uint2 uh, ul;
                    { __nv_bfloat162 t0; t0.x = h0; t0.y = h1; uh.x = *(unsigned*)&t0;
                      __nv_bfloat162 t1; t1.x = h2; t1.y = h3; uh.y = *(unsigned*)&t1; }
                    ul.x = pack_bf(s0 - __bfloat162float(h0), s1 - __bfloat162float(h1));
                    ul.y = pack_bf(s2 - __bfloat162float(h2), s3 - __bfloat162float(h3));
                    *(uint2*)(smem + aNxt + off)         = uh;
                    *(uint2*)(smem + aNxt + 16384 + off) = ul;
                }
            }
        }
        if (hn) asm volatile("cp.async.wait_group 0;" ::: "memory");
        __syncthreads();
        tap = tapn; ch = chn;
    }

    // ---- epilogue: NCHW scatter from D fragments ----
    {
        int g = lid >> 2, t = lid & 3;
        int y = y0 + warpM;
        float* pb = out + ((size_t)b << 20) + (y << 6);
#pragma unroll
        for (int mi = 0; mi < 4; ++mi) {
            int x0p = (mi << 4) + g;
#pragma unroll
            for (int nf = 0; nf < 8; ++nf) {
                int o = (warpN << 6) + (nf << 3) + (t << 1);
                float* p0 = pb + ((size_t)o << 12);
                p0[x0p]            = acc[mi][nf][0];
                p0[4096 + x0p]     = acc[mi][nf][1];
                p0[x0p + 8]        = acc[mi][nf][2];
                p0[4096 + x0p + 8] = acc[mi][nf][3];
            }
        }
    }
}

// ---------------- launch ----------------
extern "C" void kernel_launch(void* const* d_in, const int* in_sizes, int n_in,
                              void* d_out, int out_size) {
    const float* x      = (const float*)d_in[0];
    const float* offw   = (const float*)d_in[1];
    const float* offb   = (const float*)d_in[2];
    const float* conv_w = (const float*)d_in[3];
    float* out = (float*)d_out;

    static int smem_set = 0;
    if (!smem_set) {
        cudaFuncSetAttribute(k_main, cudaFuncAttributeMaxDynamicSharedMemorySize, SM_TOTAL);
        smem_set = 1;
    }

    k_txp<<<BB * HH, 256>>>(x);
    k_prep<<<(K9 * 4 * 256 * 64 + CC_ * 81 + 255) / 256, 256>>>(conv_w, offw);
    k_offsets<<<BB * 16, 256>>>(offb);
    k_main<<<BB * 32, 256, SM_TOTAL>>>(out);
}

// round 10
// speedup vs baseline: 2.5733x; 1.6273x over previous
#include <cuda_runtime.h>
#include <cuda_fp16.h>
#include <cuda_bf16.h>
#include <cstdint>

// Problem constants
#define BB 8
#define CC_ 256
#define OO 256
#define HH 64
#define WW 64
#define HWSZ 4096
#define PLANE (HH*WW*CC_)
#define K9 9

// ---------------- scratch (static __device__ — no allocation) ----------------
__device__ float g_xT[BB * PLANE];            // x in NHWC [b][y][x][c]
__device__ unsigned long long g_wO[CC_ * 81]; // offset_w packed f32x2
__device__ float g_py[BB * K9 * HWSZ];
__device__ float g_px[BB * K9 * HWSZ];
// B operand images, swizzled fp16: [tap*4+ch] -> [o:256][c:64] (32KB each)
__device__ uint4 g_wB[K9 * 4 * 2048];

// ---------------- helpers ----------------
__device__ __forceinline__ unsigned long long pack2(float v) {
    unsigned long long r; asm("mov.b64 %0, {%1, %1};" : "=l"(r) : "f"(v)); return r;
}
__device__ __forceinline__ unsigned long long fma2(unsigned long long a, unsigned long long b, unsigned long long c) {
    unsigned long long d; asm("fma.rn.f32x2 %0, %1, %2, %3;" : "=l"(d) : "l"(a), "l"(b), "l"(c)); return d;
}
__device__ __forceinline__ void unpack2(unsigned long long v, float& lo, float& hi) {
    asm("mov.b64 {%0, %1}, %2;" : "=f"(lo), "=f"(hi) : "l"(v));
}
__device__ __forceinline__ unsigned smem_u32(const void* p) {
    unsigned a;
    asm("{ .reg .u64 t; cvta.to.shared.u64 t, %1; cvt.u32.u64 %0, t; }" : "=r"(a) : "l"(p));
    return a;
}
__device__ __forceinline__ void ldsm4(unsigned& r0, unsigned& r1, unsigned& r2, unsigned& r3, unsigned addr) {
    asm volatile("ldmatrix.sync.aligned.m8n8.x4.shared.b16 {%0,%1,%2,%3}, [%4];"
                 : "=r"(r0), "=r"(r1), "=r"(r2), "=r"(r3) : "r"(addr));
}
__device__ __forceinline__ void mma16816(float* d, unsigned a0, unsigned a1, unsigned a2, unsigned a3,
                                         unsigned b0, unsigned b1) {
    asm volatile("mma.sync.aligned.m16n8k16.row.col.f32.f16.f16.f32 "
                 "{%0,%1,%2,%3}, {%4,%5,%6,%7}, {%8,%9}, {%0,%1,%2,%3};"
                 : "+f"(d[0]), "+f"(d[1]), "+f"(d[2]), "+f"(d[3])
                 : "r"(a0), "r"(a1), "r"(a2), "r"(a3), "r"(b0), "r"(b1));
}
__device__ __forceinline__ void cp16(unsigned dst, const void* src) {
    asm volatile("cp.async.cg.shared.global [%0], [%1], 16;" :: "r"(dst), "l"(src));
}
__device__ __forceinline__ unsigned pack_h2(float a, float b) {
    __half2 t = __floats2half2_rn(a, b);
    return *(unsigned*)&t;
}
__device__ __forceinline__ void samp(float py, float px, int4& id, float4& wv) {
    float fy = floorf(py), fx = floorf(px);
    int iy0 = (int)fy, ix0 = (int)fx;
    float wy1 = py - fy, wx1 = px - fx;
    float wy0 = 1.f - wy1, wx0 = 1.f - wx1;
    int iy1 = iy0 + 1, ix1 = ix0 + 1;
    bool vy0 = (iy0 >= 0) && (iy0 < HH), vy1 = (iy1 >= 0) && (iy1 < HH);
    bool vx0 = (ix0 >= 0) && (ix0 < WW), vx1 = (ix1 >= 0) && (ix1 < WW);
    int cy0 = min(max(iy0, 0), HH - 1), cy1 = min(max(iy1, 0), HH - 1);
    int cx0 = min(max(ix0, 0), WW - 1), cx1 = min(max(ix1, 0), WW - 1);
    id = make_int4(((cy0 << 6) + cx0) << 8, ((cy0 << 6) + cx1) << 8,
                   ((cy1 << 6) + cx0) << 8, ((cy1 << 6) + cx1) << 8);
    wv = make_float4((vy0 && vx0) ? wy0 * wx0 : 0.f, (vy0 && vx1) ? wy0 * wx1 : 0.f,
                     (vy1 && vx0) ? wy1 * wx0 : 0.f, (vy1 && vx1) ? wy1 * wx1 : 0.f);
}

// ---------------- kernel 1: NCHW -> NHWC transpose ----------------
__global__ __launch_bounds__(256) void k_txp(const float* __restrict__ x) {
    __shared__ float t[128][65];
    int b = blockIdx.x >> 6;
    int y = blockIdx.x & 63;
    for (int h = 0; h < 2; ++h) {
        for (int i = threadIdx.x; i < 128 * 64; i += 256) {
            int c = i >> 6, xx = i & 63;
            t[c][xx] = x[(((b << 8) + (h << 7) + c) << 12) + (y << 6) + xx];
        }
        __syncthreads();
        for (int i = threadIdx.x; i < 64 * 128; i += 256) {
            int xx = i >> 7, c = i & 127;
            g_xT[((((b << 6) + y) << 6) + xx) * 256 + (h << 7) + c] = t[c][xx];
        }
        __syncthreads();
    }
}

// ---------------- kernel 2: weight prep ----------------
__global__ void k_prep(const float* __restrict__ conv_w, const float* __restrict__ offw) {
    int idx = blockIdx.x * 256 + threadIdx.x;
    if (idx < K9 * 4 * 256 * 64) {
        int c   = idx & 63;
        int o   = (idx >> 6) & 255;
        int ch  = (idx >> 14) & 3;
        int tap = idx >> 16;
        float f = conv_w[(o * 256 + (ch << 6) + c) * 9 + tap];
        int img = tap * 4 + ch;
        unsigned off = (unsigned)((o << 7) + (c << 1));
        off ^= (unsigned)((o & 7) << 4);               // ldmatrix-friendly XOR swizzle
        ((__half*)g_wB)[img * 16384 + (off >> 1)] = __float2half_rn(f);
    }
    int j = idx - K9 * 4 * 256 * 64;
    if (j >= 0 && j < CC_ * 81) {
        int c = j / 81;
        int r = j - c * 81;
        int tap = r / 9;
        int p = r - tap * 9;
        float lo = offw[((2 * p) * 256 + c) * 9 + tap];
        float hi = offw[((2 * p + 1) * 256 + c) * 9 + tap];
        g_wO[j] = ((unsigned long long)__float_as_uint(hi) << 32) | (unsigned long long)__float_as_uint(lo);
    }
}

// ---------------- kernel 3: offset conv -> sampling coords (4 rows/block) ----------------
__global__ __launch_bounds__(256) void k_offsets(const float* __restrict__ offb) {
    __shared__ float xs[6][66][17];
    __shared__ unsigned long long ws[16][81];

    int blk = blockIdx.x;
    int b = blk >> 4;
    int y0 = (blk & 15) << 2;
    int tid = threadIdx.x;
    int ly = tid >> 6, lx = tid & 63;
    int y = y0 + ly;
    const float* plane = g_xT + ((size_t)b << 20);

    unsigned long long acc[9];
#pragma unroll
    for (int p = 0; p < 9; ++p) acc[p] = 0ull;

    for (int cc = 0; cc < 16; ++cc) {
        int c0 = cc << 4;
        for (int i = tid; i < 1584; i += 256) {
            int r = i / 264, rem = i - r * 264;
            int jj = rem >> 2, q = rem & 3;
            int yy = y0 - 1 + r, xx = jj - 1;
            float4 v = make_float4(0.f, 0.f, 0.f, 0.f);
            if (yy >= 0 && yy < HH && xx >= 0 && xx < WW)
                v = *(const float4*)(plane + ((yy << 6) + xx) * 256 + c0 + (q << 2));
            xs[r][jj][(q << 2) + 0] = v.x; xs[r][jj][(q << 2) + 1] = v.y;
            xs[r][jj][(q << 2) + 2] = v.z; xs[r][jj][(q << 2) + 3] = v.w;
        }
        for (int i = tid; i < 1296; i += 256) {
            int c = i / 81, t = i - c * 81;
            ws[c][t] = g_wO[(c0 + c) * 81 + t];
        }
        __syncthreads();
        for (int c = 0; c < 16; ++c) {
#pragma unroll
            for (int tap = 0; tap < 9; ++tap) {
                unsigned long long v2 = pack2(xs[ly + tap / 3][lx + tap % 3][c]);
#pragma unroll
                for (int p = 0; p < 9; ++p) acc[p] = fma2(v2, ws[c][tap * 9 + p], acc[p]);
            }
        }
        __syncthreads();
    }
#pragma unroll
    for (int k = 0; k < 9; ++k) {
        float dyo, dxo; unpack2(acc[k], dyo, dxo);
        dyo += offb[2 * k]; dxo += offb[2 * k + 1];
        int gi = ((b * 9 + k) << 12) + (y << 6) + lx;
        g_py[gi] = (float)(y - 1 + k / 3) + dyo;
        g_px[gi] = (float)(lx - 1 + k % 3) + dxo;
    }
}

// ---------------- kernel 4: fused gather + single-pass fp16 HMMA GEMM ----------------
// block = (b, y): M=64 pixels, N=256 outputs; 8 warps 2Mx4N, 32x64 warp tiles.
// smem: A double 2x8KB + B double 2x32KB = 80KB; 2 CTAs/SM.
#define SM_A     0
#define SM_B     16384
#define SM_TOTAL 81920

__global__ __launch_bounds__(256, 2) void k_main(float* __restrict__ out) {
    extern __shared__ char smem[];
    unsigned sb = smem_u32(smem);
    int tid = threadIdx.x;
    int w = tid >> 5, lid = tid & 31;
    int b = blockIdx.x >> 6;
    int y = blockIdx.x & 63;

    const float* plane = g_xT + ((size_t)b << 20);
    int mA = tid >> 2;                    // staging pixel 0..63
    int cq = (tid & 3) << 4;              // 16-chan strip within 64-chunk
    unsigned xm = (unsigned)((mA & 7) << 4);
    int gi0 = ((b * 9) << 12) + (y << 6) + mA;

    int warpM = w >> 2, warpN = w & 3;
    unsigned xorS  = (unsigned)((lid & 7) << 4);
    unsigned aBase = (unsigned)(((warpM << 5) + (lid & 15)) << 7) + (unsigned)((lid >> 4) << 4);
    unsigned bBase = (unsigned)(((warpN << 6) + (lid & 7) + ((lid & 16) ? 8 : 0)) << 7)
                   + (unsigned)(((lid >> 3) & 1) << 4);

    float acc[2][8][4];
#pragma unroll
    for (int mi = 0; mi < 2; ++mi)
#pragma unroll
        for (int nf = 0; nf < 8; ++nf)
#pragma unroll
            for (int q = 0; q < 4; ++q) acc[mi][nf][q] = 0.f;

    // ---- prologue: stage iter 0 (tap0, ch0) into buffer 0 ----
    {
#pragma unroll
        for (int i = 0; i < 8; ++i)
            cp16(sb + SM_B + ((tid + i * 256) << 4), g_wB + tid + i * 256);
        asm volatile("cp.async.commit_group;" ::: "memory");
        int4 id; float4 wv;
        samp(g_py[gi0], g_px[gi0], id, wv);
        const float* pb = plane + cq;
#pragma unroll
        for (int seg = 0; seg < 4; ++seg) {
            const float* p4 = pb + (seg << 2);
            float4 v00 = *(const float4*)(p4 + id.x);
            float4 v01 = *(const float4*)(p4 + id.y);
            float4 v10 = *(const float4*)(p4 + id.z);
            float4 v11 = *(const float4*)(p4 + id.w);
            float s0 = wv.x * v00.x + wv.y * v01.x + wv.z * v10.x + wv.w * v11.x;
            float s1 = wv.x * v00.y + wv.y * v01.y + wv.z * v10.y + wv.w * v11.y;
            float s2 = wv.x * v00.z + wv.y * v01.z + wv.z * v10.z + wv.w * v11.z;
            float s3 = wv.x * v00.w + wv.y * v01.w + wv.z * v10.w + wv.w * v11.w;
            unsigned off = ((unsigned)(mA << 7) + (unsigned)((cq + (seg << 2)) << 1)) ^ xm;
            uint2 u; u.x = pack_h2(s0, s1); u.y = pack_h2(s2, s3);
            *(uint2*)(smem + SM_A + off) = u;
        }
        asm volatile("cp.async.wait_group 0;" ::: "memory");
        __syncthreads();
    }

    int tap = 0, ch = 0;
    for (int it = 0; it < 36; ++it) {
        int tapn = tap + 1, chn = ch;
        if (tapn == 9) { tapn = 0; chn = ch + 1; }
        bool hn = (chn < 4);
        int cur = it & 1, nxt = cur ^ 1;
        unsigned aCur = SM_A + (unsigned)(cur << 13);
        unsigned aNxt = SM_A + (unsigned)(nxt << 13);
        unsigned bCur = SM_B + (unsigned)(cur << 15);
        unsigned bNxt = SM_B + (unsigned)(nxt << 15);

        // issue B(next) copy — overlaps the whole iteration
        if (hn) {
            const uint4* src = g_wB + (tapn * 4 + chn) * 2048;
#pragma unroll
            for (int i = 0; i < 8; ++i)
                cp16(sb + bNxt + ((tid + i * 256) << 4), src + tid + i * 256);
            asm volatile("cp.async.commit_group;" ::: "memory");
        }

        int4 id; float4 wv;
        const float* pb = plane;
        if (hn) {
            samp(g_py[gi0 + (tapn << 12)], g_px[gi0 + (tapn << 12)], id, wv);
            pb = plane + (chn << 6) + cq;
        }

        // ---- 4 k16-steps, staging for next iter interleaved ----
#pragma unroll
        for (int seg = 0; seg < 4; ++seg) {
            float4 r0, r1, r2, r3;
            if (hn) {
                const float* p4 = pb + (seg << 2);
                r0 = *(const float4*)(p4 + id.x);
                r1 = *(const float4*)(p4 + id.y);
                r2 = *(const float4*)(p4 + id.z);
                r3 = *(const float4*)(p4 + id.w);
            }
            {
                int ks = seg;
                unsigned a[2][4];
#pragma unroll
                for (int mi = 0; mi < 2; ++mi) {
                    unsigned lin = (aBase + (unsigned)(ks << 5) + (unsigned)(mi << 11)) ^ xorS;
                    ldsm4(a[mi][0], a[mi][1], a[mi][2], a[mi][3], sb + aCur + lin);
                }
#pragma unroll
                for (int nh = 0; nh < 2; ++nh) {
                    unsigned bf[4][2];
#pragma unroll
                    for (int n16 = 0; n16 < 2; ++n16) {
                        unsigned lin = (bBase + (unsigned)(ks << 5) + (unsigned)(nh << 12)
                                        + (unsigned)(n16 << 11)) ^ xorS;
                        unsigned q0, q1, q2, q3;
                        ldsm4(q0, q1, q2, q3, sb + bCur + lin);
                        bf[n16 * 2 + 0][0] = q0; bf[n16 * 2 + 0][1] = q1;
                        bf[n16 * 2 + 1][0] = q2; bf[n16 * 2 + 1][1] = q3;
                    }
#pragma unroll
                    for (int mi = 0; mi < 2; ++mi)
#pragma unroll
                        for (int nf = 0; nf < 4; ++nf)
                            mma16816(acc[mi][nh * 4 + nf], a[mi][0], a[mi][1], a[mi][2], a[mi][3],
                                     bf[nf][0], bf[nf][1]);
                }
            }
            if (hn) {
                float s0 = wv.x * r0.x + wv.y * r1.x + wv.z * r2.x + wv.w * r3.x;
                float s1 = wv.x * r0.y + wv.y * r1.y + wv.z * r2.y + wv.w * r3.y;
                float s2 = wv.x * r0.z + wv.y * r1.z + wv.z * r2.z + wv.w * r3.z;
                float s3 = wv.x * r0.w + wv.y * r1.w + wv.z * r2.w + wv.w * r3.w;
                unsigned off = ((unsigned)(mA << 7) + (unsigned)((cq + (seg << 2)) << 1)) ^ xm;
                uint2 u; u.x = pack_h2(s0, s1); u.y = pack_h2(s2, s3);
                *(uint2*)(smem + aNxt + off) = u;
            }
        }
        if (hn) asm volatile("cp.async.wait_group 0;" ::: "memory");
        __syncthreads();
        tap = tapn; ch = chn;
    }

    // ---- epilogue: NCHW scatter from D fragments ----
    {
        int g = lid >> 2, t = lid & 3;
        float* pb = out + ((size_t)b << 20) + (y << 6);
#pragma unroll
        for (int mi = 0; mi < 2; ++mi) {
            int x0p = (warpM << 5) + (mi << 4) + g;
#pragma unroll
            for (int nf = 0; nf < 8; ++nf) {
                int o = (warpN << 6) + (nf << 3) + (t << 1);
                float* p0 = pb + ((size_t)o << 12);
                p0[x0p]            = acc[mi][nf][0];
                p0[4096 + x0p]     = acc[mi][nf][1];
                p0[x0p + 8]        = acc[mi][nf][2];
                p0[4096 + x0p + 8] = acc[mi][nf][3];
            }
        }
    }
}

// ---------------- launch ----------------
extern "C" void kernel_launch(void* const* d_in, const int* in_sizes, int n_in,
                              void* d_out, int out_size) {
    const float* x      = (const float*)d_in[0];
    const float* offw   = (const float*)d_in[1];
    const float* offb   = (const float*)d_in[2];
    const float* conv_w = (const float*)d_in[3];
    float* out = (float*)d_out;

    static int smem_set = 0;
    if (!smem_set) {
        cudaFuncSetAttribute(k_main, cudaFuncAttributeMaxDynamicSharedMemorySize, SM_TOTAL);
        smem_set = 1;
    }

    k_txp<<<BB * HH, 256>>>(x);
    k_prep<<<(K9 * 4 * 256 * 64 + CC_ * 81 + 255) / 256, 256>>>(conv_w, offw);
    k_offsets<<<BB * 16, 256>>>(offb);
    k_main<<<BB * HH, 256, SM_TOTAL>>>(out);
}

// round 11
// speedup vs baseline: 3.3530x; 1.3030x over previous
#include <cuda_runtime.h>
#include <cuda_fp16.h>
#include <cuda_bf16.h>
#include <cstdint>

// Problem constants
#define BB 8
#define CC_ 256
#define OO 256
#define HH 64
#define WW 64
#define HWSZ 4096
#define PLANE (HH*WW*CC_)
#define K9 9

// ---------------- scratch (static __device__ — no allocation) ----------------
__device__ float  g_xT[BB * PLANE];           // x in NHWC fp32 (offset conv)
__device__ __half g_xH[BB * PLANE];           // x in NHWC fp16 (gather)
__device__ unsigned long long g_wO[CC_ * 81]; // offset_w packed f32x2
__device__ float g_py[BB * K9 * HWSZ];
__device__ float g_px[BB * K9 * HWSZ];
// B operand images, swizzled fp16: [tap*4+ch] -> [o:256][c:64] (32KB each)
__device__ uint4 g_wB[K9 * 4 * 2048];

// ---------------- helpers ----------------
__device__ __forceinline__ unsigned long long pack2(float v) {
    unsigned long long r; asm("mov.b64 %0, {%1, %1};" : "=l"(r) : "f"(v)); return r;
}
__device__ __forceinline__ unsigned long long fma2(unsigned long long a, unsigned long long b, unsigned long long c) {
    unsigned long long d; asm("fma.rn.f32x2 %0, %1, %2, %3;" : "=l"(d) : "l"(a), "l"(b), "l"(c)); return d;
}
__device__ __forceinline__ void unpack2(unsigned long long v, float& lo, float& hi) {
    asm("mov.b64 {%0, %1}, %2;" : "=f"(lo), "=f"(hi) : "l"(v));
}
__device__ __forceinline__ unsigned smem_u32(const void* p) {
    unsigned a;
    asm("{ .reg .u64 t; cvta.to.shared.u64 t, %1; cvt.u32.u64 %0, t; }" : "=r"(a) : "l"(p));
    return a;
}
__device__ __forceinline__ void ldsm4(unsigned& r0, unsigned& r1, unsigned& r2, unsigned& r3, unsigned addr) {
    asm volatile("ldmatrix.sync.aligned.m8n8.x4.shared.b16 {%0,%1,%2,%3}, [%4];"
                 : "=r"(r0), "=r"(r1), "=r"(r2), "=r"(r3) : "r"(addr));
}
__device__ __forceinline__ void mma16816(float* d, unsigned a0, unsigned a1, unsigned a2, unsigned a3,
                                         unsigned b0, unsigned b1) {
    asm volatile("mma.sync.aligned.m16n8k16.row.col.f32.f16.f16.f32 "
                 "{%0,%1,%2,%3}, {%4,%5,%6,%7}, {%8,%9}, {%0,%1,%2,%3};"
                 : "+f"(d[0]), "+f"(d[1]), "+f"(d[2]), "+f"(d[3])
                 : "r"(a0), "r"(a1), "r"(a2), "r"(a3), "r"(b0), "r"(b1));
}
__device__ __forceinline__ void cp16(unsigned dst, const void* src) {
    asm volatile("cp.async.cg.shared.global [%0], [%1], 16;" :: "r"(dst), "l"(src));
}
__device__ __forceinline__ unsigned pack_h2(float a, float b) {
    __half2 t = __floats2half2_rn(a, b);
    return *(unsigned*)&t;
}
__device__ __forceinline__ void samp(float py, float px, int4& id, float4& wv) {
    float fy = floorf(py), fx = floorf(px);
    int iy0 = (int)fy, ix0 = (int)fx;
    float wy1 = py - fy, wx1 = px - fx;
    float wy0 = 1.f - wy1, wx0 = 1.f - wx1;
    int iy1 = iy0 + 1, ix1 = ix0 + 1;
    bool vy0 = (iy0 >= 0) && (iy0 < HH), vy1 = (iy1 >= 0) && (iy1 < HH);
    bool vx0 = (ix0 >= 0) && (ix0 < WW), vx1 = (ix1 >= 0) && (ix1 < WW);
    int cy0 = min(max(iy0, 0), HH - 1), cy1 = min(max(iy1, 0), HH - 1);
    int cx0 = min(max(ix0, 0), WW - 1), cx1 = min(max(ix1, 0), WW - 1);
    id = make_int4(((cy0 << 6) + cx0) << 8, ((cy0 << 6) + cx1) << 8,
                   ((cy1 << 6) + cx0) << 8, ((cy1 << 6) + cx1) << 8);
    wv = make_float4((vy0 && vx0) ? wy0 * wx0 : 0.f, (vy0 && vx1) ? wy0 * wx1 : 0.f,
                     (vy1 && vx0) ? wy1 * wx0 : 0.f, (vy1 && vx1) ? wy1 * wx1 : 0.f);
}

// ---------------- kernel 1: fused NCHW->NHWC transpose (fp32+fp16) + weight prep ----------------
#define TXP_BLOCKS (BB * HH)
__global__ __launch_bounds__(256) void k_txp_prep(const float* __restrict__ x,
                                                  const float* __restrict__ conv_w,
                                                  const float* __restrict__ offw) {
    if (blockIdx.x < TXP_BLOCKS) {
        __shared__ float t[128][65];
        int b = blockIdx.x >> 6;
        int y = blockIdx.x & 63;
        for (int h = 0; h < 2; ++h) {
            for (int i = threadIdx.x; i < 128 * 64; i += 256) {
                int c = i >> 6, xx = i & 63;
                t[c][xx] = x[(((b << 8) + (h << 7) + c) << 12) + (y << 6) + xx];
            }
            __syncthreads();
            for (int i = threadIdx.x; i < 64 * 128; i += 256) {
                int xx = i >> 7, c = i & 127;
                float v = t[c][xx];
                size_t o = ((((size_t)(b << 6) + y) << 6) + xx) * 256 + (h << 7) + c;
                g_xT[o] = v;
                g_xH[o] = __float2half_rn(v);
            }
            __syncthreads();
        }
        return;
    }
    int idx = (blockIdx.x - TXP_BLOCKS) * 256 + threadIdx.x;
    if (idx < K9 * 4 * 256 * 64) {
        int c   = idx & 63;
        int o   = (idx >> 6) & 255;
        int ch  = (idx >> 14) & 3;
        int tap = idx >> 16;
        float f = conv_w[(o * 256 + (ch << 6) + c) * 9 + tap];
        int img = tap * 4 + ch;
        unsigned off = (unsigned)((o << 7) + (c << 1));
        off ^= (unsigned)((o & 7) << 4);               // ldmatrix-friendly XOR swizzle
        ((__half*)g_wB)[img * 16384 + (off >> 1)] = __float2half_rn(f);
    }
    int j = idx - K9 * 4 * 256 * 64;
    if (j >= 0 && j < CC_ * 81) {
        int c = j / 81;
        int r = j - c * 81;
        int tap = r / 9;
        int p = r - tap * 9;
        float lo = offw[((2 * p) * 256 + c) * 9 + tap];
        float hi = offw[((2 * p + 1) * 256 + c) * 9 + tap];
        g_wO[j] = ((unsigned long long)__float_as_uint(hi) << 32) | (unsigned long long)__float_as_uint(lo);
    }
}

// ---------------- kernel 2: offset conv -> sampling coords (fp32 path, 4 rows/block) ----------------
__global__ __launch_bounds__(256) void k_offsets(const float* __restrict__ offb) {
    __shared__ float xs[6][66][17];
    __shared__ unsigned long long ws[16][81];

    int blk = blockIdx.x;
    int b = blk >> 4;
    int y0 = (blk & 15) << 2;
    int tid = threadIdx.x;
    int ly = tid >> 6, lx = tid & 63;
    int y = y0 + ly;
    const float* plane = g_xT + ((size_t)b << 20);

    unsigned long long acc[9];
#pragma unroll
    for (int p = 0; p < 9; ++p) acc[p] = 0ull;

    for (int cc = 0; cc < 16; ++cc) {
        int c0 = cc << 4;
        for (int i = tid; i < 1584; i += 256) {
            int r = i / 264, rem = i - r * 264;
            int jj = rem >> 2, q = rem & 3;
            int yy = y0 - 1 + r, xx = jj - 1;
            float4 v = make_float4(0.f, 0.f, 0.f, 0.f);
            if (yy >= 0 && yy < HH && xx >= 0 && xx < WW)
                v = *(const float4*)(plane + ((yy << 6) + xx) * 256 + c0 + (q << 2));
            xs[r][jj][(q << 2) + 0] = v.x; xs[r][jj][(q << 2) + 1] = v.y;
            xs[r][jj][(q << 2) + 2] = v.z; xs[r][jj][(q << 2) + 3] = v.w;
        }
        for (int i = tid; i < 1296; i += 256) {
            int c = i / 81, t = i - c * 81;
            ws[c][t] = g_wO[(c0 + c) * 81 + t];
        }
        __syncthreads();
        for (int c = 0; c < 16; ++c) {
#pragma unroll
            for (int tap = 0; tap < 9; ++tap) {
                unsigned long long v2 = pack2(xs[ly + tap / 3][lx + tap % 3][c]);
#pragma unroll
                for (int p = 0; p < 9; ++p) acc[p] = fma2(v2, ws[c][tap * 9 + p], acc[p]);
            }
        }
        __syncthreads();
    }
#pragma unroll
    for (int k = 0; k < 9; ++k) {
        float dyo, dxo; unpack2(acc[k], dyo, dxo);
        dyo += offb[2 * k]; dxo += offb[2 * k + 1];
        int gi = ((b * 9 + k) << 12) + (y << 6) + lx;
        g_py[gi] = (float)(y - 1 + k / 3) + dyo;
        g_px[gi] = (float)(lx - 1 + k % 3) + dxo;
    }
}

// ---------------- kernel 3: fused fp16 gather + single-pass fp16 HMMA GEMM ----------------
// block = (b, y): M=64 pixels, N=256 outputs; 8 warps 2Mx4N, 32x64 warp tiles.
// smem: A double 2x8KB + B double 2x32KB = 80KB; 2 CTAs/SM.
#define SM_A     0
#define SM_B     16384
#define SM_TOTAL 81920

__global__ __launch_bounds__(256, 2) void k_main(float* __restrict__ out) {
    extern __shared__ char smem[];
    unsigned sb = smem_u32(smem);
    int tid = threadIdx.x;
    int w = tid >> 5, lid = tid & 31;
    int b = blockIdx.x >> 6;
    int y = blockIdx.x & 63;

    const __half* planeH = g_xH + ((size_t)b << 20);
    int mA = tid >> 2;                    // staging pixel 0..63
    int cq = (tid & 3) << 4;              // 16-chan strip within 64-chunk
    unsigned xm = (unsigned)((mA & 7) << 4);
    int gi0 = ((b * 9) << 12) + (y << 6) + mA;

    int warpM = w >> 2, warpN = w & 3;
    unsigned xorS  = (unsigned)((lid & 7) << 4);
    unsigned aBase = (unsigned)(((warpM << 5) + (lid & 15)) << 7) + (unsigned)((lid >> 4) << 4);
    unsigned bBase = (unsigned)(((warpN << 6) + (lid & 7) + ((lid & 16) ? 8 : 0)) << 7)
                   + (unsigned)(((lid >> 3) & 1) << 4);

    float acc[2][8][4];
#pragma unroll
    for (int mi = 0; mi < 2; ++mi)
#pragma unroll
        for (int nf = 0; nf < 8; ++nf)
#pragma unroll
            for (int q = 0; q < 4; ++q) acc[mi][nf][q] = 0.f;

    // ---- prologue: stage iter 0 (tap0, ch0) into buffer 0 ----
    {
#pragma unroll
        for (int i = 0; i < 8; ++i)
            cp16(sb + SM_B + ((tid + i * 256) << 4), g_wB + tid + i * 256);
        asm volatile("cp.async.commit_group;" ::: "memory");
        int4 id; float4 wv;
        samp(g_py[gi0], g_px[gi0], id, wv);
        const __half* pbh = planeH + cq;
#pragma unroll
        for (int seg = 0; seg < 2; ++seg) {
            const __half* p4 = pbh + (seg << 3);
            uint4 u0 = *(const uint4*)(p4 + id.x);
            uint4 u1 = *(const uint4*)(p4 + id.y);
            uint4 u2 = *(const uint4*)(p4 + id.z);
            uint4 u3 = *(const uint4*)(p4 + id.w);
            float s[8];
#pragma unroll
            for (int q = 0; q < 4; ++q) {
                float2 f0 = __half22float2(((const __half2*)&u0)[q]);
                float2 f1 = __half22float2(((const __half2*)&u1)[q]);
                float2 f2 = __half22float2(((const __half2*)&u2)[q]);
                float2 f3 = __half22float2(((const __half2*)&u3)[q]);
                s[2 * q]     = wv.x * f0.x + wv.y * f1.x + wv.z * f2.x + wv.w * f3.x;
                s[2 * q + 1] = wv.x * f0.y + wv.y * f1.y + wv.z * f2.y + wv.w * f3.y;
            }
            unsigned off = ((unsigned)(mA << 7) + (unsigned)((cq + (seg << 3)) << 1)) ^ xm;
            uint4 st;
            st.x = pack_h2(s[0], s[1]); st.y = pack_h2(s[2], s[3]);
            st.z = pack_h2(s[4], s[5]); st.w = pack_h2(s[6], s[7]);
            *(uint4*)(smem + SM_A + off) = st;
        }
        asm volatile("cp.async.wait_group 0;" ::: "memory");
        __syncthreads();
    }

    int tap = 0, ch = 0;
    for (int it = 0; it < 36; ++it) {
        int tapn = tap + 1, chn = ch;
        if (tapn == 9) { tapn = 0; chn = ch + 1; }
        bool hn = (chn < 4);
        int cur = it & 1, nxt = cur ^ 1;
        unsigned aCur = SM_A + (unsigned)(cur << 13);
        unsigned aNxt = SM_A + (unsigned)(nxt << 13);
        unsigned bCur = SM_B + (unsigned)(cur << 15);
        unsigned bNxt = SM_B + (unsigned)(nxt << 15);

        // issue B(next) copy — overlaps the whole iteration
        if (hn) {
            const uint4* src = g_wB + (tapn * 4 + chn) * 2048;
#pragma unroll
            for (int i = 0; i < 8; ++i)
                cp16(sb + bNxt + ((tid + i * 256) << 4), src + tid + i * 256);
            asm volatile("cp.async.commit_group;" ::: "memory");
        }

        int4 id; float4 wv;
        const __half* pbh = planeH;
        if (hn) {
            samp(g_py[gi0 + (tapn << 12)], g_px[gi0 + (tapn << 12)], id, wv);
            pbh = planeH + (chn << 6) + cq;
        }

        // ---- 4 k16-steps; A staging for next iter interleaved with ks=0,1 ----
#pragma unroll
        for (int ks = 0; ks < 4; ++ks) {
            uint4 u0, u1, u2, u3;
            bool st = hn && (ks < 2);
            if (st) {
                const __half* p4 = pbh + (ks << 3);
                u0 = *(const uint4*)(p4 + id.x);
                u1 = *(const uint4*)(p4 + id.y);
                u2 = *(const uint4*)(p4 + id.z);
                u3 = *(const uint4*)(p4 + id.w);
            }
            {
                unsigned a[2][4];
#pragma unroll
                for (int mi = 0; mi < 2; ++mi) {
                    unsigned lin = (aBase + (unsigned)(ks << 5) + (unsigned)(mi << 11)) ^ xorS;
                    ldsm4(a[mi][0], a[mi][1], a[mi][2], a[mi][3], sb + aCur + lin);
                }
#pragma unroll
                for (int nh = 0; nh < 2; ++nh) {
                    unsigned bf[4][2];
#pragma unroll
                    for (int n16 = 0; n16 < 2; ++n16) {
                        unsigned lin = (bBase + (unsigned)(ks << 5) + (unsigned)(nh << 12)
                                        + (unsigned)(n16 << 11)) ^ xorS;
                        unsigned q0, q1, q2, q3;
                        ldsm4(q0, q1, q2, q3, sb + bCur + lin);
                        bf[n16 * 2 + 0][0] = q0; bf[n16 * 2 + 0][1] = q1;
                        bf[n16 * 2 + 1][0] = q2; bf[n16 * 2 + 1][1] = q3;
                    }
#pragma unroll
                    for (int mi = 0; mi < 2; ++mi)
#pragma unroll
                        for (int nf = 0; nf < 4; ++nf)
                            mma16816(acc[mi][nh * 4 + nf], a[mi][0], a[mi][1], a[mi][2], a[mi][3],
                                     bf[nf][0], bf[nf][1]);
                }
            }
            if (st) {
                float s[8];
#pragma unroll
                for (int q = 0; q < 4; ++q) {
                    float2 f0 = __half22float2(((const __half2*)&u0)[q]);
                    float2 f1 = __half22float2(((const __half2*)&u1)[q]);
                    float2 f2 = __half22float2(((const __half2*)&u2)[q]);
                    float2 f3 = __half22float2(((const __half2*)&u3)[q]);
                    s[2 * q]     = wv.x * f0.x + wv.y * f1.x + wv.z * f2.x + wv.w * f3.x;
                    s[2 * q + 1] = wv.x * f0.y + wv.y * f1.y + wv.z * f2.y + wv.w * f3.y;
                }
                unsigned off = ((unsigned)(mA << 7) + (unsigned)((cq + (ks << 3)) << 1)) ^ xm;
                uint4 stv;
                stv.x = pack_h2(s[0], s[1]); stv.y = pack_h2(s[2], s[3]);
                stv.z = pack_h2(s[4], s[5]); stv.w = pack_h2(s[6], s[7]);
                *(uint4*)(smem + aNxt + off) = stv;
            }
        }
        if (hn) asm volatile("cp.async.wait_group 0;" ::: "memory");
        __syncthreads();
        tap = tapn; ch = chn;
    }

    // ---- epilogue: NCHW scatter from D fragments ----
    {
        int g = lid >> 2, t = lid & 3;
        float* pb = out + ((size_t)b << 20) + (y << 6);
#pragma unroll
        for (int mi = 0; mi < 2; ++mi) {
            int x0p = (warpM << 5) + (mi << 4) + g;
#pragma unroll
            for (int nf = 0; nf < 8; ++nf) {
                int o = (warpN << 6) + (nf << 3) + (t << 1);
                float* p0 = pb + ((size_t)o << 12);
                p0[x0p]            = acc[mi][nf][0];
                p0[4096 + x0p]     = acc[mi][nf][1];
                p0[x0p + 8]        = acc[mi][nf][2];
                p0[4096 + x0p + 8] = acc[mi][nf][3];
            }
        }
    }
}

// ---------------- launch ----------------
extern "C" void kernel_launch(void* const* d_in, const int* in_sizes, int n_in,
                              void* d_out, int out_size) {
    const float* x      = (const float*)d_in[0];
    const float* offw   = (const float*)d_in[1];
    const float* offb   = (const float*)d_in[2];
    const float* conv_w = (const float*)d_in[3];
    float* out = (float*)d_out;

    static int smem_set = 0;
    if (!smem_set) {
        cudaFuncSetAttribute(k_main, cudaFuncAttributeMaxDynamicSharedMemorySize, SM_TOTAL);
        smem_set = 1;
    }

    int prep_blocks = (K9 * 4 * 256 * 64 + CC_ * 81 + 255) / 256;
    k_txp_prep<<<TXP_BLOCKS + prep_blocks, 256>>>(x, conv_w, offw);
    k_offsets<<<BB * 16, 256>>>(offb);
    k_main<<<BB * HH, 256, SM_TOTAL>>>(out);
}

// round 12
// speedup vs baseline: 3.4205x; 1.0202x over previous
#include <cuda_runtime.h>
#include <cuda_fp16.h>
#include <cuda_bf16.h>
#include <cstdint>

// Problem constants
#define BB 8
#define CC_ 256
#define OO 256
#define HH 64
#define WW 64
#define HWSZ 4096
#define PLANE (HH*WW*CC_)
#define K9 9

// ---------------- scratch (static __device__ — no allocation) ----------------
__device__ float  g_xT[BB * PLANE];           // x in NHWC fp32 (offset conv)
__device__ __half g_xH[BB * PLANE];           // x in NHWC fp16 (gather)
__device__ float g_py[BB * K9 * HWSZ];
__device__ float g_px[BB * K9 * HWSZ];
// main-conv B images, swizzled fp16: [tap*4+ch] -> [o:256][c:64] (32KB each)
__device__ uint4 g_wB[K9 * 4 * 2048];
// offset-conv B images, swizzled bf16 hi/lo: [chunk=tap*4+ch] -> [n:32][k:64] (4KB each)
__device__ uint4 g_oBhi[36 * 256];
__device__ uint4 g_oBlo[36 * 256];

// ---------------- helpers ----------------
__device__ __forceinline__ unsigned smem_u32(const void* p) {
    unsigned a;
    asm("{ .reg .u64 t; cvta.to.shared.u64 t, %1; cvt.u32.u64 %0, t; }" : "=r"(a) : "l"(p));
    return a;
}
__device__ __forceinline__ void ldsm4(unsigned& r0, unsigned& r1, unsigned& r2, unsigned& r3, unsigned addr) {
    asm volatile("ldmatrix.sync.aligned.m8n8.x4.shared.b16 {%0,%1,%2,%3}, [%4];"
                 : "=r"(r0), "=r"(r1), "=r"(r2), "=r"(r3) : "r"(addr));
}
__device__ __forceinline__ void mma16816(float* d, unsigned a0, unsigned a1, unsigned a2, unsigned a3,
                                         unsigned b0, unsigned b1) {
    asm volatile("mma.sync.aligned.m16n8k16.row.col.f32.f16.f16.f32 "
                 "{%0,%1,%2,%3}, {%4,%5,%6,%7}, {%8,%9}, {%0,%1,%2,%3};"
                 : "+f"(d[0]), "+f"(d[1]), "+f"(d[2]), "+f"(d[3])
                 : "r"(a0), "r"(a1), "r"(a2), "r"(a3), "r"(b0), "r"(b1));
}
__device__ __forceinline__ void mma16816bf(float* d, unsigned a0, unsigned a1, unsigned a2, unsigned a3,
                                           unsigned b0, unsigned b1) {
    asm volatile("mma.sync.aligned.m16n8k16.row.col.f32.bf16.bf16.f32 "
                 "{%0,%1,%2,%3}, {%4,%5,%6,%7}, {%8,%9}, {%0,%1,%2,%3};"
                 : "+f"(d[0]), "+f"(d[1]), "+f"(d[2]), "+f"(d[3])
                 : "r"(a0), "r"(a1), "r"(a2), "r"(a3), "r"(b0), "r"(b1));
}
__device__ __forceinline__ void cp16(unsigned dst, const void* src) {
    asm volatile("cp.async.cg.shared.global [%0], [%1], 16;" :: "r"(dst), "l"(src));
}
__device__ __forceinline__ unsigned pack_h2(float a, float b) {
    __half2 t = __floats2half2_rn(a, b);
    return *(unsigned*)&t;
}
__device__ __forceinline__ unsigned pack_bf2(float a, float b) {
    __nv_bfloat162 t; t.x = __float2bfloat16(a); t.y = __float2bfloat16(b);
    return *(unsigned*)&t;
}
__device__ __forceinline__ void samp(float py, float px, int4& id, float4& wv) {
    float fy = floorf(py), fx = floorf(px);
    int iy0 = (int)fy, ix0 = (int)fx;
    float wy1 = py - fy, wx1 = px - fx;
    float wy0 = 1.f - wy1, wx0 = 1.f - wx1;
    int iy1 = iy0 + 1, ix1 = ix0 + 1;
    bool vy0 = (iy0 >= 0) && (iy0 < HH), vy1 = (iy1 >= 0) && (iy1 < HH);
    bool vx0 = (ix0 >= 0) && (ix0 < WW), vx1 = (ix1 >= 0) && (ix1 < WW);
    int cy0 = min(max(iy0, 0), HH - 1), cy1 = min(max(iy1, 0), HH - 1);
    int cx0 = min(max(ix0, 0), WW - 1), cx1 = min(max(ix1, 0), WW - 1);
    id = make_int4(((cy0 << 6) + cx0) << 8, ((cy0 << 6) + cx1) << 8,
                   ((cy1 << 6) + cx0) << 8, ((cy1 << 6) + cx1) << 8);
    wv = make_float4((vy0 && vx0) ? wy0 * wx0 : 0.f, (vy0 && vx1) ? wy0 * wx1 : 0.f,
                     (vy1 && vx0) ? wy1 * wx0 : 0.f, (vy1 && vx1) ? wy1 * wx1 : 0.f);
}

// ---------------- kernel 1: fused NCHW->NHWC transpose (fp32+fp16) + weight prep ----------------
#define TXP_BLOCKS (BB * HH)
__global__ __launch_bounds__(256) void k_txp_prep(const float* __restrict__ x,
                                                  const float* __restrict__ conv_w,
                                                  const float* __restrict__ offw) {
    if (blockIdx.x < TXP_BLOCKS) {
        __shared__ float t[128][65];
        int b = blockIdx.x >> 6;
        int y = blockIdx.x & 63;
        for (int h = 0; h < 2; ++h) {
            for (int i = threadIdx.x; i < 128 * 64; i += 256) {
                int c = i >> 6, xx = i & 63;
                t[c][xx] = x[(((b << 8) + (h << 7) + c) << 12) + (y << 6) + xx];
            }
            __syncthreads();
            for (int i = threadIdx.x; i < 64 * 128; i += 256) {
                int xx = i >> 7, c = i & 127;
                float v = t[c][xx];
                size_t o = ((((size_t)(b << 6) + y) << 6) + xx) * 256 + (h << 7) + c;
                g_xT[o] = v;
                g_xH[o] = __float2half_rn(v);
            }
            __syncthreads();
        }
        return;
    }
    int idx = (blockIdx.x - TXP_BLOCKS) * 256 + threadIdx.x;
    if (idx < K9 * 4 * 256 * 64) {
        int c   = idx & 63;
        int o   = (idx >> 6) & 255;
        int ch  = (idx >> 14) & 3;
        int tap = idx >> 16;
        float f = conv_w[(o * 256 + (ch << 6) + c) * 9 + tap];
        int img = tap * 4 + ch;
        unsigned off = (unsigned)((o << 7) + (c << 1));
        off ^= (unsigned)((o & 7) << 4);               // ldmatrix-friendly XOR swizzle
        ((__half*)g_wB)[img * 16384 + (off >> 1)] = __float2half_rn(f);
    }
    int j = idx - K9 * 4 * 256 * 64;
    if (j >= 0 && j < 36 * 32 * 64) {
        int kk    = j & 63;
        int n     = (j >> 6) & 31;
        int chunk = j >> 11;             // tap*4+ch
        int tap   = chunk >> 2;
        int ch    = chunk & 3;
        float f = (n < 18) ? offw[(n * 256 + (ch << 6) + kk) * 9 + tap] : 0.f;
        __nv_bfloat16 hi = __float2bfloat16(f);
        __nv_bfloat16 lo = __float2bfloat16(f - __bfloat162float(hi));
        unsigned off = (unsigned)((n << 7) + (kk << 1));
        off ^= (unsigned)((n & 7) << 4);
        ((__nv_bfloat16*)g_oBhi)[chunk * 2048 + (off >> 1)] = hi;
        ((__nv_bfloat16*)g_oBlo)[chunk * 2048 + (off >> 1)] = lo;
    }
}

// ---------------- kernel 2: offset conv via 3-pass bf16 HMMA -> sampling coords ----------------
// block = (b, row-pair): M=128 px, N=24 used (pad 32), K = 36 chunks x 64.
// 8 warps, warp tile 16(M) x 32(N). smem A 32KB + B 8KB = 40KB static; 3 CTAs/SM.
__global__ __launch_bounds__(256, 3) void k_offs(const float* __restrict__ offb) {
    __shared__ char smem[40960];         // [0:16K) A hi, [16K:32K) A lo, [32K:36K) B hi, [36K:40K) B lo
    unsigned sb = smem_u32(smem);
    int tid = threadIdx.x;
    int w = tid >> 5, lid = tid & 31;
    int b = blockIdx.x >> 5;
    int y0 = (blockIdx.x & 31) << 1;

    const float* plane = g_xT + ((size_t)b << 20);
    int mA = tid >> 1;                   // staging pixel 0..127
    int half = (tid & 1) << 5;           // 32-k strip within chunk
    int yP = y0 + (mA >> 6);             // output row of staged pixel
    int xP = mA & 63;
    unsigned rb = (unsigned)(mA << 7) + (unsigned)(half << 1);
    unsigned xmS = (unsigned)((mA & 7) << 4);

    unsigned xorS  = (unsigned)((lid & 7) << 4);
    unsigned aBase = (unsigned)(((w << 4) + (lid & 15)) << 7) + (unsigned)((lid >> 4) << 4);
    unsigned bBase = (unsigned)(((lid & 7) + ((lid & 16) ? 8 : 0)) << 7)
                   + (unsigned)(((lid >> 3) & 1) << 4);

    float acc[3][4];
#pragma unroll
    for (int nf = 0; nf < 3; ++nf)
#pragma unroll
        for (int q = 0; q < 4; ++q) acc[nf][q] = 0.f;

    for (int chunk = 0; chunk < 36; ++chunk) {
        int tap = chunk >> 2, ch = chunk & 3;
        // ---- B copy (8KB) ----
        cp16(sb + 32768 + (tid << 4), g_oBhi + chunk * 256 + tid);
        cp16(sb + 36864 + (tid << 4), g_oBlo + chunk * 256 + tid);
        asm volatile("cp.async.commit_group;" ::: "memory");
        // ---- A stage: shifted window, fp32 -> bf16 hi/lo ----
        {
            int ty = tap / 3, tx = tap - ty * 3;
            int yy = yP - 1 + ty, xx = xP - 1 + tx;
            bool ok = (yy >= 0) && (yy < HH) && (xx >= 0) && (xx < WW);
            const float* src = plane + ((yy << 6) + xx) * 256 + (ch << 6) + half;
#pragma unroll
            for (int j = 0; j < 8; ++j) {
                float4 v = ok ? *(const float4*)(src + (j << 2)) : make_float4(0.f, 0.f, 0.f, 0.f);
                __nv_bfloat16 h0 = __float2bfloat16(v.x), h1 = __float2bfloat16(v.y);
                __nv_bfloat16 h2 = __float2bfloat16(v.z), h3 = __float2bfloat16(v.w);
                unsigned off = (rb + (unsigned)(j << 3)) ^ xmS;
                uint2 uh, ul;
                { __nv_bfloat162 t0; t0.x = h0; t0.y = h1; uh.x = *(unsigned*)&t0;
                  __nv_bfloat162 t1; t1.x = h2; t1.y = h3; uh.y = *(unsigned*)&t1; }
                ul.x = pack_bf2(v.x - __bfloat162float(h0), v.y - __bfloat162float(h1));
                ul.y = pack_bf2(v.z - __bfloat162float(h2), v.w - __bfloat162float(h3));
                *(uint2*)(smem + off)         = uh;
                *(uint2*)(smem + 16384 + off) = ul;
            }
        }
        asm volatile("cp.async.wait_group 0;" ::: "memory");
        __syncthreads();

        // ---- 4 k16-steps, 3 passes (hh, hl, lh), nf=0..2 (n 0..23) ----
#pragma unroll
        for (int ks = 0; ks < 4; ++ks) {
            unsigned lin = (aBase + (unsigned)(ks << 5)) ^ xorS;
            unsigned ah0, ah1, ah2, ah3, al0, al1, al2, al3;
            ldsm4(ah0, ah1, ah2, ah3, sb + lin);
            ldsm4(al0, al1, al2, al3, sb + 16384 + lin);
            unsigned bh[4][2], bl[4][2];
#pragma unroll
            for (int n16 = 0; n16 < 2; ++n16) {
                unsigned bln = (bBase + (unsigned)(ks << 5) + (unsigned)(n16 << 11)) ^ xorS;
                unsigned q0, q1, q2, q3;
                ldsm4(q0, q1, q2, q3, sb + 32768 + bln);
                bh[n16 * 2 + 0][0] = q0; bh[n16 * 2 + 0][1] = q1;
                bh[n16 * 2 + 1][0] = q2; bh[n16 * 2 + 1][1] = q3;
                ldsm4(q0, q1, q2, q3, sb + 36864 + bln);
                bl[n16 * 2 + 0][0] = q0; bl[n16 * 2 + 0][1] = q1;
                bl[n16 * 2 + 1][0] = q2; bl[n16 * 2 + 1][1] = q3;
            }
#pragma unroll
            for (int nf = 0; nf < 3; ++nf) {
                mma16816bf(acc[nf], ah0, ah1, ah2, ah3, bh[nf][0], bh[nf][1]);
                mma16816bf(acc[nf], ah0, ah1, ah2, ah3, bl[nf][0], bl[nf][1]);
                mma16816bf(acc[nf], al0, al1, al2, al3, bh[nf][0], bh[nf][1]);
            }
        }
        __syncthreads();
    }

    // ---- epilogue: coords = base + offset + bias ----
#pragma unroll
    for (int nf = 0; nf < 3; ++nf) {
        int k = (nf << 2) + (lid & 3);
        if (k < 9) {
            float oy = offb[2 * k], ox = offb[2 * k + 1];
            int ky = k / 3, kx = k - ky * 3;
#pragma unroll
            for (int h = 0; h < 2; ++h) {
                int m = (w << 4) + (lid >> 2) + (h << 3);
                int ym = y0 + (m >> 6), xm = m & 63;
                int gi = ((b * 9 + k) << 12) + (ym << 6) + xm;
                g_py[gi] = (float)(ym - 1 + ky) + acc[nf][h * 2]     + oy;
                g_px[gi] = (float)(xm - 1 + kx) + acc[nf][h * 2 + 1] + ox;
            }
        }
    }
}

// ---------------- kernel 3: fused fp16 gather + single-pass fp16 HMMA GEMM ----------------
// block = (b, y): M=64 pixels, N=256 outputs; 8 warps 2Mx4N, 32x64 warp tiles.
// smem: A double 2x8KB + B double 2x32KB = 80KB; 2 CTAs/SM.
#define SM_A     0
#define SM_B     16384
#define SM_TOTAL 81920

__global__ __launch_bounds__(256, 2) void k_main(float* __restrict__ out) {
    extern __shared__ char smem[];
    unsigned sb = smem_u32(smem);
    int tid = threadIdx.x;
    int w = tid >> 5, lid = tid & 31;
    int b = blockIdx.x >> 6;
    int y = blockIdx.x & 63;

    const __half* planeH = g_xH + ((size_t)b << 20);
    int mA = tid >> 2;                    // staging pixel 0..63
    int cq = (tid & 3) << 4;              // 16-chan strip within 64-chunk
    unsigned xm = (unsigned)((mA & 7) << 4);
    int gi0 = ((b * 9) << 12) + (y << 6) + mA;

    int warpM = w >> 2, warpN = w & 3;
    unsigned xorS  = (unsigned)((lid & 7) << 4);
    unsigned aBase = (unsigned)(((warpM << 5) + (lid & 15)) << 7) + (unsigned)((lid >> 4) << 4);
    unsigned bBase = (unsigned)(((warpN << 6) + (lid & 7) + ((lid & 16) ? 8 : 0)) << 7)
                   + (unsigned)(((lid >> 3) & 1) << 4);

    float acc[2][8][4];
#pragma unroll
    for (int mi = 0; mi < 2; ++mi)
#pragma unroll
        for (int nf = 0; nf < 8; ++nf)
#pragma unroll
            for (int q = 0; q < 4; ++q) acc[mi][nf][q] = 0.f;

    // ---- prologue: stage iter 0 (tap0, ch0) into buffer 0 ----
    {
#pragma unroll
        for (int i = 0; i < 8; ++i)
            cp16(sb + SM_B + ((tid + i * 256) << 4), g_wB + tid + i * 256);
        asm volatile("cp.async.commit_group;" ::: "memory");
        int4 id; float4 wv;
        samp(g_py[gi0], g_px[gi0], id, wv);
        const __half* pbh = planeH + cq;
#pragma unroll
        for (int seg = 0; seg < 2; ++seg) {
            const __half* p4 = pbh + (seg << 3);
            uint4 u0 = *(const uint4*)(p4 + id.x);
            uint4 u1 = *(const uint4*)(p4 + id.y);
            uint4 u2 = *(const uint4*)(p4 + id.z);
            uint4 u3 = *(const uint4*)(p4 + id.w);
            float s[8];
#pragma unroll
            for (int q = 0; q < 4; ++q) {
                float2 f0 = __half22float2(((const __half2*)&u0)[q]);
                float2 f1 = __half22float2(((const __half2*)&u1)[q]);
                float2 f2 = __half22float2(((const __half2*)&u2)[q]);
                float2 f3 = __half22float2(((const __half2*)&u3)[q]);
                s[2 * q]     = wv.x * f0.x + wv.y * f1.x + wv.z * f2.x + wv.w * f3.x;
                s[2 * q + 1] = wv.x * f0.y + wv.y * f1.y + wv.z * f2.y + wv.w * f3.y;
            }
            unsigned off = ((unsigned)(mA << 7) + (unsigned)((cq + (seg << 3)) << 1)) ^ xm;
            uint4 st;
            st.x = pack_h2(s[0], s[1]); st.y = pack_h2(s[2], s[3]);
            st.z = pack_h2(s[4], s[5]); st.w = pack_h2(s[6], s[7]);
            *(uint4*)(smem + SM_A + off) = st;
        }
        asm volatile("cp.async.wait_group 0;" ::: "memory");
        __syncthreads();
    }

    int tap = 0, ch = 0;
    for (int it = 0; it < 36; ++it) {
        int tapn = tap + 1, chn = ch;
        if (tapn == 9) { tapn = 0; chn = ch + 1; }
        bool hn = (chn < 4);
        int cur = it & 1, nxt = cur ^ 1;
        unsigned aCur = SM_A + (unsigned)(cur << 13);
        unsigned aNxt = SM_A + (unsigned)(nxt << 13);
        unsigned bCur = SM_B + (unsigned)(cur << 15);
        unsigned bNxt = SM_B + (unsigned)(nxt << 15);

        // issue B(next) copy — overlaps the whole iteration
        if (hn) {
            const uint4* src = g_wB + (tapn * 4 + chn) * 2048;
#pragma unroll
            for (int i = 0; i < 8; ++i)
                cp16(sb + bNxt + ((tid + i * 256) << 4), src + tid + i * 256);
            asm volatile("cp.async.commit_group;" ::: "memory");
        }

        int4 id; float4 wv;
        const __half* pbh = planeH;
        if (hn) {
            samp(g_py[gi0 + (tapn << 12)], g_px[gi0 + (tapn << 12)], id, wv);
            pbh = planeH + (chn << 6) + cq;
        }

        // ---- 4 k16-steps; A staging for next iter interleaved with ks=0,1 ----
#pragma unroll
        for (int ks = 0; ks < 4; ++ks) {
            uint4 u0, u1, u2, u3;
            bool st = hn && (ks < 2);
            if (st) {
                const __half* p4 = pbh + (ks << 3);
                u0 = *(const uint4*)(p4 + id.x);
                u1 = *(const uint4*)(p4 + id.y);
                u2 = *(const uint4*)(p4 + id.z);
                u3 = *(const uint4*)(p4 + id.w);
            }
            {
                unsigned a[2][4];
#pragma unroll
                for (int mi = 0; mi < 2; ++mi) {
                    unsigned lin = (aBase + (unsigned)(ks << 5) + (unsigned)(mi << 11)) ^ xorS;
                    ldsm4(a[mi][0], a[mi][1], a[mi][2], a[mi][3], sb + aCur + lin);
                }
#pragma unroll
                for (int nh = 0; nh < 2; ++nh) {
                    unsigned bf[4][2];
#pragma unroll
                    for (int n16 = 0; n16 < 2; ++n16) {
                        unsigned lin = (bBase + (unsigned)(ks << 5) + (unsigned)(nh << 12)
                                        + (unsigned)(n16 << 11)) ^ xorS;
                        unsigned q0, q1, q2, q3;
                        ldsm4(q0, q1, q2, q3, sb + bCur + lin);
                        bf[n16 * 2 + 0][0] = q0; bf[n16 * 2 + 0][1] = q1;
                        bf[n16 * 2 + 1][0] = q2; bf[n16 * 2 + 1][1] = q3;
                    }
#pragma unroll
                    for (int mi = 0; mi < 2; ++mi)
#pragma unroll
                        for (int nf = 0; nf < 4; ++nf)
                            mma16816(acc[mi][nh * 4 + nf], a[mi][0], a[mi][1], a[mi][2], a[mi][3],
                                     bf[nf][0], bf[nf][1]);
                }
            }
            if (st) {
                float s[8];
#pragma unroll
                for (int q = 0; q < 4; ++q) {
                    float2 f0 = __half22float2(((const __half2*)&u0)[q]);
                    float2 f1 = __half22float2(((const __half2*)&u1)[q]);
                    float2 f2 = __half22float2(((const __half2*)&u2)[q]);
                    float2 f3 = __half22float2(((const __half2*)&u3)[q]);
                    s[2 * q]     = wv.x * f0.x + wv.y * f1.x + wv.z * f2.x + wv.w * f3.x;
                    s[2 * q + 1] = wv.x * f0.y + wv.y * f1.y + wv.z * f2.y + wv.w * f3.y;
                }
                unsigned off = ((unsigned)(mA << 7) + (unsigned)((cq + (ks << 3)) << 1)) ^ xm;
                uint4 stv;
                stv.x = pack_h2(s[0], s[1]); stv.y = pack_h2(s[2], s[3]);
                stv.z = pack_h2(s[4], s[5]); stv.w = pack_h2(s[6], s[7]);
                *(uint4*)(smem + aNxt + off) = stv;
            }
        }
        if (hn) asm volatile("cp.async.wait_group 0;" ::: "memory");
        __syncthreads();
        tap = tapn; ch = chn;
    }

    // ---- epilogue: NCHW scatter from D fragments ----
    {
        int g = lid >> 2, t = lid & 3;
        float* pb = out + ((size_t)b << 20) + (y << 6);
#pragma unroll
        for (int mi = 0; mi < 2; ++mi) {
            int x0p = (warpM << 5) + (mi << 4) + g;
#pragma unroll
            for (int nf = 0; nf < 8; ++nf) {
                int o = (warpN << 6) + (nf << 3) + (t << 1);
                float* p0 = pb + ((size_t)o << 12);
                p0[x0p]            = acc[mi][nf][0];
                p0[4096 + x0p]     = acc[mi][nf][1];
                p0[x0p + 8]        = acc[mi][nf][2];
                p0[4096 + x0p + 8] = acc[mi][nf][3];
            }
        }
    }
}

// ---------------- launch ----------------
extern "C" void kernel_launch(void* const* d_in, const int* in_sizes, int n_in,
                              void* d_out, int out_size) {
    const float* x      = (const float*)d_in[0];
    const float* offw   = (const float*)d_in[1];
    const float* offb   = (const float*)d_in[2];
    const float* conv_w = (const float*)d_in[3];
    float* out = (float*)d_out;

    static int smem_set = 0;
    if (!smem_set) {
        cudaFuncSetAttribute(k_main, cudaFuncAttributeMaxDynamicSharedMemorySize, SM_TOTAL);
        smem_set = 1;
    }

    int prep_blocks = (K9 * 4 * 256 * 64 + 36 * 32 * 64 + 255) / 256;
    k_txp_prep<<<TXP_BLOCKS + prep_blocks, 256>>>(x, conv_w, offw);
    k_offs<<<BB * 32, 256>>>(offb);
    k_main<<<BB * HH, 256, SM_TOTAL>>>(out);
}

// round 13
// speedup vs baseline: 4.3212x; 1.2633x over previous
#include <cuda_runtime.h>
#include <cuda_fp16.h>
#include <cuda_bf16.h>
#include <cstdint>

// Problem constants
#define BB 8
#define CC_ 256
#define OO 256
#define HH 64
#define WW 64
#define HWSZ 4096
#define PLANE (HH*WW*CC_)
#define K9 9

// ---------------- scratch (static __device__ — no allocation) ----------------
__device__ float  g_xT[BB * PLANE];           // x in NHWC fp32 (offset conv)
__device__ __half g_xH[BB * PLANE];           // x in NHWC fp16 (gather)
__device__ float g_py[BB * K9 * HWSZ];
__device__ float g_px[BB * K9 * HWSZ];
// main-conv B images, swizzled fp16: [tap*4+ch] -> [o:256][c:64] (32KB each)
__device__ uint4 g_wB[K9 * 4 * 2048];
// offset-conv B images, swizzled bf16 hi/lo: [chunk=tap*4+ch] -> [n:32][k:64] (4KB each)
__device__ uint4 g_oBhi[36 * 256];
__device__ uint4 g_oBlo[36 * 256];

// ---------------- helpers ----------------
__device__ __forceinline__ unsigned smem_u32(const void* p) {
    unsigned a;
    asm("{ .reg .u64 t; cvta.to.shared.u64 t, %1; cvt.u32.u64 %0, t; }" : "=r"(a) : "l"(p));
    return a;
}
__device__ __forceinline__ void ldsm4(unsigned& r0, unsigned& r1, unsigned& r2, unsigned& r3, unsigned addr) {
    asm volatile("ldmatrix.sync.aligned.m8n8.x4.shared.b16 {%0,%1,%2,%3}, [%4];"
                 : "=r"(r0), "=r"(r1), "=r"(r2), "=r"(r3) : "r"(addr));
}
__device__ __forceinline__ void mma16816(float* d, unsigned a0, unsigned a1, unsigned a2, unsigned a3,
                                         unsigned b0, unsigned b1) {
    asm volatile("mma.sync.aligned.m16n8k16.row.col.f32.f16.f16.f32 "
                 "{%0,%1,%2,%3}, {%4,%5,%6,%7}, {%8,%9}, {%0,%1,%2,%3};"
                 : "+f"(d[0]), "+f"(d[1]), "+f"(d[2]), "+f"(d[3])
                 : "r"(a0), "r"(a1), "r"(a2), "r"(a3), "r"(b0), "r"(b1));
}
__device__ __forceinline__ void mma16816bf(float* d, unsigned a0, unsigned a1, unsigned a2, unsigned a3,
                                           unsigned b0, unsigned b1) {
    asm volatile("mma.sync.aligned.m16n8k16.row.col.f32.bf16.bf16.f32 "
                 "{%0,%1,%2,%3}, {%4,%5,%6,%7}, {%8,%9}, {%0,%1,%2,%3};"
                 : "+f"(d[0]), "+f"(d[1]), "+f"(d[2]), "+f"(d[3])
                 : "r"(a0), "r"(a1), "r"(a2), "r"(a3), "r"(b0), "r"(b1));
}
__device__ __forceinline__ void cp16(unsigned dst, const void* src) {
    asm volatile("cp.async.cg.shared.global [%0], [%1], 16;" :: "r"(dst), "l"(src));
}
__device__ __forceinline__ unsigned pack_h2(float a, float b) {
    __half2 t = __floats2half2_rn(a, b);
    return *(unsigned*)&t;
}
__device__ __forceinline__ unsigned pack_bf2(float a, float b) {
    __nv_bfloat162 t; t.x = __float2bfloat16(a); t.y = __float2bfloat16(b);
    return *(unsigned*)&t;
}
__device__ __forceinline__ void samp(float py, float px, int4& id, float4& wv) {
    float fy = floorf(py), fx = floorf(px);
    int iy0 = (int)fy, ix0 = (int)fx;
    float wy1 = py - fy, wx1 = px - fx;
    float wy0 = 1.f - wy1, wx0 = 1.f - wx1;
    int iy1 = iy0 + 1, ix1 = ix0 + 1;
    bool vy0 = (iy0 >= 0) && (iy0 < HH), vy1 = (iy1 >= 0) && (iy1 < HH);
    bool vx0 = (ix0 >= 0) && (ix0 < WW), vx1 = (ix1 >= 0) && (ix1 < WW);
    int cy0 = min(max(iy0, 0), HH - 1), cy1 = min(max(iy1, 0), HH - 1);
    int cx0 = min(max(ix0, 0), WW - 1), cx1 = min(max(ix1, 0), WW - 1);
    id = make_int4(((cy0 << 6) + cx0) << 8, ((cy0 << 6) + cx1) << 8,
                   ((cy1 << 6) + cx0) << 8, ((cy1 << 6) + cx1) << 8);
    wv = make_float4((vy0 && vx0) ? wy0 * wx0 : 0.f, (vy0 && vx1) ? wy0 * wx1 : 0.f,
                     (vy1 && vx0) ? wy1 * wx0 : 0.f, (vy1 && vx1) ? wy1 * wx1 : 0.f);
}

// ---------------- kernel 1: fused NCHW->NHWC transpose (fp32+fp16) + weight prep ----------------
#define TXP_BLOCKS (BB * HH)
__global__ __launch_bounds__(256) void k_txp_prep(const float* __restrict__ x,
                                                  const float* __restrict__ conv_w,
                                                  const float* __restrict__ offw) {
    if (blockIdx.x < TXP_BLOCKS) {
        __shared__ float t[128][65];
        int b = blockIdx.x >> 6;
        int y = blockIdx.x & 63;
        for (int h = 0; h < 2; ++h) {
            for (int i = threadIdx.x; i < 128 * 64; i += 256) {
                int c = i >> 6, xx = i & 63;
                t[c][xx] = x[(((b << 8) + (h << 7) + c) << 12) + (y << 6) + xx];
            }
            __syncthreads();
            for (int i = threadIdx.x; i < 64 * 128; i += 256) {
                int xx = i >> 7, c = i & 127;
                float v = t[c][xx];
                size_t o = ((((size_t)(b << 6) + y) << 6) + xx) * 256 + (h << 7) + c;
                g_xT[o] = v;
                g_xH[o] = __float2half_rn(v);
            }
            __syncthreads();
        }
        return;
    }
    int idx = (blockIdx.x - TXP_BLOCKS) * 256 + threadIdx.x;
    if (idx < K9 * 4 * 256 * 64) {
        int c   = idx & 63;
        int o   = (idx >> 6) & 255;
        int ch  = (idx >> 14) & 3;
        int tap = idx >> 16;
        float f = conv_w[(o * 256 + (ch << 6) + c) * 9 + tap];
        int img = tap * 4 + ch;
        unsigned off = (unsigned)((o << 7) + (c << 1));
        off ^= (unsigned)((o & 7) << 4);               // ldmatrix-friendly XOR swizzle
        ((__half*)g_wB)[img * 16384 + (off >> 1)] = __float2half_rn(f);
    }
    int j = idx - K9 * 4 * 256 * 64;
    if (j >= 0 && j < 36 * 32 * 64) {
        int kk    = j & 63;
        int n     = (j >> 6) & 31;
        int chunk = j >> 11;             // tap*4+ch
        int tap   = chunk >> 2;
        int ch    = chunk & 3;
        float f = (n < 18) ? offw[(n * 256 + (ch << 6) + kk) * 9 + tap] : 0.f;
        __nv_bfloat16 hi = __float2bfloat16(f);
        __nv_bfloat16 lo = __float2bfloat16(f - __bfloat162float(hi));
        unsigned off = (unsigned)((n << 7) + (kk << 1));
        off ^= (unsigned)((n & 7) << 4);
        ((__nv_bfloat16*)g_oBhi)[chunk * 2048 + (off >> 1)] = hi;
        ((__nv_bfloat16*)g_oBlo)[chunk * 2048 + (off >> 1)] = lo;
    }
}

// ---------------- kernel 2: offset conv, panel-staged A + 3-pass bf16 HMMA ----------------
// block = (b, row-pair): M=128 px, N=24 used (pad 32), K = 4 ch-chunks x 64.
// A panel: 4 rows x 66 cols x 64ch staged ONCE per ch-chunk; 9 taps read shifted addresses.
// smem: panel hi 33792 + panel lo 33792 + B ring 2x8192 = 83968; 2 CTAs/SM.
#define OFP_HI   0
#define OFP_LO   33792
#define OFP_B    67584
#define OFP_TOT  83968

__global__ __launch_bounds__(256, 2) void k_offs(const float* __restrict__ offb) {
    extern __shared__ char smem[];
    unsigned sb = smem_u32(smem);
    int tid = threadIdx.x;
    int w = tid >> 5, lid = tid & 31;
    int b = blockIdx.x >> 5;
    int y0 = (blockIdx.x & 31) << 1;

    const float* plane = g_xT + ((size_t)b << 20);
    int r = w >> 2;                      // output row within pair
    int cbase = (w & 3) << 4;            // col base of warp's 16-pixel strip
    unsigned xorS = (unsigned)((lid & 7) << 4);
    unsigned bBase = (unsigned)(((lid & 7) + ((lid & 16) ? 8 : 0)) << 7)
                   + (unsigned)(((lid >> 3) & 1) << 4);

    float acc[3][4];
#pragma unroll
    for (int nf = 0; nf < 3; ++nf)
#pragma unroll
        for (int q = 0; q < 4; ++q) acc[nf][q] = 0.f;

    // prologue: B(t=0) + panel(ch=0)
    {
        cp16(sb + OFP_B + (tid << 4), g_oBhi + tid);
        cp16(sb + OFP_B + 4096 + (tid << 4), g_oBlo + tid);
        asm volatile("cp.async.commit_group;" ::: "memory");
    }
    for (int ch_stage = 0; ch_stage <= 0; ++ch_stage) { }  // (panel staged below in loop body for ch 0)

    // stage panel for ch=0
    {
        for (int p = tid; p < 264; p += 256) {
            int row = p / 66, col = p - row * 66;
            int yy = y0 - 1 + row, xx = col - 1;
            bool ok = (yy >= 0) && (yy < HH) && (xx >= 0) && (xx < WW);
            const float* src = plane + ((yy << 6) + xx) * 256;
            unsigned pb = (unsigned)(p << 7);
            unsigned sw = (unsigned)((p & 7) << 4);
#pragma unroll
            for (int j = 0; j < 16; ++j) {
                float4 v = ok ? *(const float4*)(src + (j << 2)) : make_float4(0.f, 0.f, 0.f, 0.f);
                __nv_bfloat16 h0 = __float2bfloat16(v.x), h1 = __float2bfloat16(v.y);
                __nv_bfloat16 h2 = __float2bfloat16(v.z), h3 = __float2bfloat16(v.w);
                uint2 uh, ul;
                { __nv_bfloat162 t0; t0.x = h0; t0.y = h1; uh.x = *(unsigned*)&t0;
                  __nv_bfloat162 t1; t1.x = h2; t1.y = h3; uh.y = *(unsigned*)&t1; }
                ul.x = pack_bf2(v.x - __bfloat162float(h0), v.y - __bfloat162float(h1));
                ul.y = pack_bf2(v.z - __bfloat162float(h2), v.w - __bfloat162float(h3));
                unsigned off = pb + (unsigned)((j << 3) ^ sw);
                *(uint2*)(smem + OFP_HI + off) = uh;
                *(uint2*)(smem + OFP_LO + off) = ul;
            }
        }
    }

    for (int t = 0; t < 36; ++t) {
        int ch = t / 9, tap = t - ch * 9;
        // commit B(t+1)
        if (t < 35) {
            int t1 = t + 1;
            int chk = (t1 - (t1 / 9) * 9) * 4 + (t1 / 9);
            unsigned dst = sb + OFP_B + (unsigned)((t1 & 1) << 13);
            cp16(dst + (tid << 4), g_oBhi + chk * 256 + tid);
            cp16(dst + 4096 + (tid << 4), g_oBlo + chk * 256 + tid);
            asm volatile("cp.async.commit_group;" ::: "memory");
        }
        // re-stage panel at each new ch-chunk
        if (tap == 0 && t > 0) {
            __syncthreads();             // all warps done reading old panel
            for (int p = tid; p < 264; p += 256) {
                int row = p / 66, col = p - row * 66;
                int yy = y0 - 1 + row, xx = col - 1;
                bool ok = (yy >= 0) && (yy < HH) && (xx >= 0) && (xx < WW);
                const float* src = plane + ((yy << 6) + xx) * 256 + (ch << 6);
                unsigned pb = (unsigned)(p << 7);
                unsigned sw = (unsigned)((p & 7) << 4);
#pragma unroll
                for (int j = 0; j < 16; ++j) {
                    float4 v = ok ? *(const float4*)(src + (j << 2)) : make_float4(0.f, 0.f, 0.f, 0.f);
                    __nv_bfloat16 h0 = __float2bfloat16(v.x), h1 = __float2bfloat16(v.y);
                    __nv_bfloat16 h2 = __float2bfloat16(v.z), h3 = __float2bfloat16(v.w);
                    uint2 uh, ul;
                    { __nv_bfloat162 t0; t0.x = h0; t0.y = h1; uh.x = *(unsigned*)&t0;
                      __nv_bfloat162 t1; t1.x = h2; t1.y = h3; uh.y = *(unsigned*)&t1; }
                    ul.x = pack_bf2(v.x - __bfloat162float(h0), v.y - __bfloat162float(h1));
                    ul.y = pack_bf2(v.z - __bfloat162float(h2), v.w - __bfloat162float(h3));
                    unsigned off = pb + (unsigned)((j << 3) ^ sw);
                    *(uint2*)(smem + OFP_HI + off) = uh;
                    *(uint2*)(smem + OFP_LO + off) = ul;
                }
            }
        }
        if (t < 35) { asm volatile("cp.async.wait_group 1;" ::: "memory"); }
        else        { asm volatile("cp.async.wait_group 0;" ::: "memory"); }
        __syncthreads();

        // ---- MMAs: 4 k16 steps, 3 passes, nf=0..2 ----
        int ty = tap / 3, tx = tap - ty * 3;
        int tb = (r + ty) * 66 + cbase + tx;
        unsigned bbuf = OFP_B + (unsigned)((t & 1) << 13);
#pragma unroll
        for (int ks = 0; ks < 4; ++ks) {
            unsigned p = (unsigned)(tb + (lid & 15));
            unsigned lin = (p << 7) + (unsigned)(ks << 5) + (unsigned)((lid >> 4) << 4);
            lin ^= (p & 7) << 4;
            unsigned ah0, ah1, ah2, ah3, al0, al1, al2, al3;
            ldsm4(ah0, ah1, ah2, ah3, sb + OFP_HI + lin);
            ldsm4(al0, al1, al2, al3, sb + OFP_LO + lin);
            unsigned bh[4][2], bl[4][2];
#pragma unroll
            for (int n16 = 0; n16 < 2; ++n16) {
                unsigned bln = (bBase + (unsigned)(ks << 5) + (unsigned)(n16 << 11)) ^ xorS;
                unsigned q0, q1, q2, q3;
                ldsm4(q0, q1, q2, q3, sb + bbuf + bln);
                bh[n16 * 2 + 0][0] = q0; bh[n16 * 2 + 0][1] = q1;
                bh[n16 * 2 + 1][0] = q2; bh[n16 * 2 + 1][1] = q3;
                ldsm4(q0, q1, q2, q3, sb + bbuf + 4096 + bln);
                bl[n16 * 2 + 0][0] = q0; bl[n16 * 2 + 0][1] = q1;
                bl[n16 * 2 + 1][0] = q2; bl[n16 * 2 + 1][1] = q3;
            }
#pragma unroll
            for (int nf = 0; nf < 3; ++nf) {
                mma16816bf(acc[nf], ah0, ah1, ah2, ah3, bh[nf][0], bh[nf][1]);
                mma16816bf(acc[nf], ah0, ah1, ah2, ah3, bl[nf][0], bl[nf][1]);
                mma16816bf(acc[nf], al0, al1, al2, al3, bh[nf][0], bh[nf][1]);
            }
        }
    }

    // ---- epilogue: coords = base + offset + bias ----
#pragma unroll
    for (int nf = 0; nf < 3; ++nf) {
        int k = (nf << 2) + (lid & 3);
        if (k < 9) {
            float oy = offb[2 * k], ox = offb[2 * k + 1];
            int ky = k / 3, kx = k - ky * 3;
#pragma unroll
            for (int h = 0; h < 2; ++h) {
                int m = (w << 4) + (lid >> 2) + (h << 3);
                int ym = y0 + (m >> 6), xm = m & 63;
                int gi = ((b * 9 + k) << 12) + (ym << 6) + xm;
                g_py[gi] = (float)(ym - 1 + ky) + acc[nf][h * 2]     + oy;
                g_px[gi] = (float)(xm - 1 + kx) + acc[nf][h * 2 + 1] + ox;
            }
        }
    }
}

// ---------------- kernel 3: fused fp16 gather + single-pass fp16 HMMA GEMM ----------------
// block = (b, y): M=64 pixels, N=256 outputs; 8 warps 2Mx4N, 32x64 warp tiles.
// smem: A double 2x8KB + B double 2x32KB = 80KB; 2 CTAs/SM.
#define SM_A     0
#define SM_B     16384
#define SM_TOTAL 81920

__global__ __launch_bounds__(256, 2) void k_main(float* __restrict__ out) {
    extern __shared__ char smem[];
    unsigned sb = smem_u32(smem);
    int tid = threadIdx.x;
    int w = tid >> 5, lid = tid & 31;
    int b = blockIdx.x >> 6;
    int y = blockIdx.x & 63;

    const __half* planeH = g_xH + ((size_t)b << 20);
    int mA = tid >> 2;                    // staging pixel 0..63
    int cq = (tid & 3) << 4;              // 16-chan strip within 64-chunk
    unsigned xm = (unsigned)((mA & 7) << 4);
    int gi0 = ((b * 9) << 12) + (y << 6) + mA;

    int warpM = w >> 2, warpN = w & 3;
    unsigned xorS  = (unsigned)((lid & 7) << 4);
    unsigned aBase = (unsigned)(((warpM << 5) + (lid & 15)) << 7) + (unsigned)((lid >> 4) << 4);
    unsigned bBase = (unsigned)(((warpN << 6) + (lid & 7) + ((lid & 16) ? 8 : 0)) << 7)
                   + (unsigned)(((lid >> 3) & 1) << 4);

    float acc[2][8][4];
#pragma unroll
    for (int mi = 0; mi < 2; ++mi)
#pragma unroll
        for (int nf = 0; nf < 8; ++nf)
#pragma unroll
            for (int q = 0; q < 4; ++q) acc[mi][nf][q] = 0.f;

    // ---- prologue: stage iter 0 (tap0, ch0) into buffer 0 ----
    {
#pragma unroll
        for (int i = 0; i < 8; ++i)
            cp16(sb + SM_B + ((tid + i * 256) << 4), g_wB + tid + i * 256);
        asm volatile("cp.async.commit_group;" ::: "memory");
        int4 id; float4 wv;
        samp(g_py[gi0], g_px[gi0], id, wv);
        const __half* pbh = planeH + cq;
#pragma unroll
        for (int seg = 0; seg < 2; ++seg) {
            const __half* p4 = pbh + (seg << 3);
            uint4 u0 = *(const uint4*)(p4 + id.x);
            uint4 u1 = *(const uint4*)(p4 + id.y);
            uint4 u2 = *(const uint4*)(p4 + id.z);
            uint4 u3 = *(const uint4*)(p4 + id.w);
            float s[8];
#pragma unroll
            for (int q = 0; q < 4; ++q) {
                float2 f0 = __half22float2(((const __half2*)&u0)[q]);
                float2 f1 = __half22float2(((const __half2*)&u1)[q]);
                float2 f2 = __half22float2(((const __half2*)&u2)[q]);
                float2 f3 = __half22float2(((const __half2*)&u3)[q]);
                s[2 * q]     = wv.x * f0.x + wv.y * f1.x + wv.z * f2.x + wv.w * f3.x;
                s[2 * q + 1] = wv.x * f0.y + wv.y * f1.y + wv.z * f2.y + wv.w * f3.y;
            }
            unsigned off = ((unsigned)(mA << 7) + (unsigned)((cq + (seg << 3)) << 1)) ^ xm;
            uint4 st;
            st.x = pack_h2(s[0], s[1]); st.y = pack_h2(s[2], s[3]);
            st.z = pack_h2(s[4], s[5]); st.w = pack_h2(s[6], s[7]);
            *(uint4*)(smem + SM_A + off) = st;
        }
        asm volatile("cp.async.wait_group 0;" ::: "memory");
        __syncthreads();
    }

    int tap = 0, ch = 0;
    for (int it = 0; it < 36; ++it) {
        int tapn = tap + 1, chn = ch;
        if (tapn == 9) { tapn = 0; chn = ch + 1; }
        bool hn = (chn < 4);
        int cur = it & 1, nxt = cur ^ 1;
        unsigned aCur = SM_A + (unsigned)(cur << 13);
        unsigned aNxt = SM_A + (unsigned)(nxt << 13);
        unsigned bCur = SM_B + (unsigned)(cur << 15);
        unsigned bNxt = SM_B + (unsigned)(nxt << 15);

        // issue B(next) copy — overlaps the whole iteration
        if (hn) {
            const uint4* src = g_wB + (tapn * 4 + chn) * 2048;
#pragma unroll
            for (int i = 0; i < 8; ++i)
                cp16(sb + bNxt + ((tid + i * 256) << 4), src + tid + i * 256);
            asm volatile("cp.async.commit_group;" ::: "memory");
        }

        int4 id; float4 wv;
        const __half* pbh = planeH;
        if (hn) {
            samp(g_py[gi0 + (tapn << 12)], g_px[gi0 + (tapn << 12)], id, wv);
            pbh = planeH + (chn << 6) + cq;
            // prefetch the 4 corner lines (one lane per pixel; each chunk = one 128B line)
            if ((tid & 3) == 0) {
                const __half* pf = planeH + (chn << 6);
                asm volatile("prefetch.global.L1 [%0];" :: "l"(pf + id.x));
                asm volatile("prefetch.global.L1 [%0];" :: "l"(pf + id.y));
                asm volatile("prefetch.global.L1 [%0];" :: "l"(pf + id.z));
                asm volatile("prefetch.global.L1 [%0];" :: "l"(pf + id.w));
            }
        }

        // ---- 4 k16-steps; A staging for next iter interleaved with ks=0,1 ----
#pragma unroll
        for (int ks = 0; ks < 4; ++ks) {
            uint4 u0, u1, u2, u3;
            bool st = hn && (ks < 2);
            if (st) {
                const __half* p4 = pbh + (ks << 3);
                u0 = *(const uint4*)(p4 + id.x);
                u1 = *(const uint4*)(p4 + id.y);
                u2 = *(const uint4*)(p4 + id.z);
                u3 = *(const uint4*)(p4 + id.w);
            }
            {
                unsigned a[2][4];
#pragma unroll
                for (int mi = 0; mi < 2; ++mi) {
                    unsigned lin = (aBase + (unsigned)(ks << 5) + (unsigned)(mi << 11)) ^ xorS;
                    ldsm4(a[mi][0], a[mi][1], a[mi][2], a[mi][3], sb + aCur + lin);
                }
#pragma unroll
                for (int nh = 0; nh < 2; ++nh) {
                    unsigned bf[4][2];
#pragma unroll
                    for (int n16 = 0; n16 < 2; ++n16) {
                        unsigned lin = (bBase + (unsigned)(ks << 5) + (unsigned)(nh << 12)
                                        + (unsigned)(n16 << 11)) ^ xorS;
                        unsigned q0, q1, q2, q3;
                        ldsm4(q0, q1, q2, q3, sb + bCur + lin);
                        bf[n16 * 2 + 0][0] = q0; bf[n16 * 2 + 0][1] = q1;
                        bf[n16 * 2 + 1][0] = q2; bf[n16 * 2 + 1][1] = q3;
                    }
#pragma unroll
                    for (int mi = 0; mi < 2; ++mi)
#pragma unroll
                        for (int nf = 0; nf < 4; ++nf)
                            mma16816(acc[mi][nh * 4 + nf], a[mi][0], a[mi][1], a[mi][2], a[mi][3],
                                     bf[nf][0], bf[nf][1]);
                }
            }
            if (st) {
                float s[8];
#pragma unroll
                for (int q = 0; q < 4; ++q) {
                    float2 f0 = __half22float2(((const __half2*)&u0)[q]);
                    float2 f1 = __half22float2(((const __half2*)&u1)[q]);
                    float2 f2 = __half22float2(((const __half2*)&u2)[q]);
                    float2 f3 = __half22float2(((const __half2*)&u3)[q]);
                    s[2 * q]     = wv.x * f0.x + wv.y * f1.x + wv.z * f2.x + wv.w * f3.x;
                    s[2 * q + 1] = wv.x * f0.y + wv.y * f1.y + wv.z * f2.y + wv.w * f3.y;
                }
                unsigned off = ((unsigned)(mA << 7) + (unsigned)((cq + (ks << 3)) << 1)) ^ xm;
                uint4 stv;
                stv.x = pack_h2(s[0], s[1]); stv.y = pack_h2(s[2], s[3]);
                stv.z = pack_h2(s[4], s[5]); stv.w = pack_h2(s[6], s[7]);
                *(uint4*)(smem + aNxt + off) = stv;
            }
        }
        if (hn) asm volatile("cp.async.wait_group 0;" ::: "memory");
        __syncthreads();
        tap = tapn; ch = chn;
    }

    // ---- epilogue: NCHW scatter from D fragments ----
    {
        int g = lid >> 2, t = lid & 3;
        float* pb = out + ((size_t)b << 20) + (y << 6);
#pragma unroll
        for (int mi = 0; mi < 2; ++mi) {
            int x0p = (warpM << 5) + (mi << 4) + g;
#pragma unroll
            for (int nf = 0; nf < 8; ++nf) {
                int o = (warpN << 6) + (nf << 3) + (t << 1);
                float* p0 = pb + ((size_t)o << 12);
                p0[x0p]            = acc[mi][nf][0];
                p0[4096 + x0p]     = acc[mi][nf][1];
                p0[x0p + 8]        = acc[mi][nf][2];
                p0[4096 + x0p + 8] = acc[mi][nf][3];
            }
        }
    }
}

// ---------------- launch ----------------
extern "C" void kernel_launch(void* const* d_in, const int* in_sizes, int n_in,
                              void* d_out, int out_size) {
    const float* x      = (const float*)d_in[0];
    const float* offw   = (const float*)d_in[1];
    const float* offb   = (const float*)d_in[2];
    const float* conv_w = (const float*)d_in[3];
    float* out = (float*)d_out;

    static int smem_set = 0;
    if (!smem_set) {
        cudaFuncSetAttribute(k_main, cudaFuncAttributeMaxDynamicSharedMemorySize, SM_TOTAL);
        cudaFuncSetAttribute(k_offs, cudaFuncAttributeMaxDynamicSharedMemorySize, OFP_TOT);
        smem_set = 1;
    }

    int prep_blocks = (K9 * 4 * 256 * 64 + 36 * 32 * 64 + 255) / 256;
    k_txp_prep<<<TXP_BLOCKS + prep_blocks, 256>>>(x, conv_w, offw);
    k_offs<<<BB * 32, 256, OFP_TOT>>>(offb);
    k_main<<<BB * HH, 256, SM_TOTAL>>>(out);
}